// round 14
// baseline (speedup 1.0000x reference)
#include <cuda_runtime.h>
#include <cuda_bf16.h>
#include <math.h>
#include <stdint.h>

#define BB 2
#define TT 2048
#define DD 1024
#define HH 16
#define HDIM 64
#define ROWS (BB * TT)
#define D3 (3 * DD)
#define D4 (4 * DD)

// fp32 scratch
__device__ float g_x2 [ROWS * DD];
__device__ float g_y  [ROWS * DD];       // attention out (tf32-rounded)
__device__ float g_xnf[ROWS * DD];       // ln out (tf32-rounded, reused)
__device__ float g_fcf[ROWS * D4];       // gelu out (tf32-rounded)
__device__ float g_qk [ROWS * 2 * DD];   // [q(scaled)|k] fp32 tf32-rounded
__device__ float g_vt [ROWS * DD];       // V^T per head: [b][h][d][token]
__device__ float g_wattnf[D3 * DD];      // transposed tf32 weights [N,K]
__device__ float g_wprojf[DD * DD];
__device__ float g_wfcf [D4 * DD];
__device__ float g_woutf[DD * D4];

__device__ __forceinline__ uint32_t smem_u32(const void* p) {
    uint32_t a;
    asm("{ .reg .u64 t; cvta.to.shared.u64 t, %1; cvt.u32.u64 %0, t; }"
        : "=r"(a) : "l"(p));
    return a;
}

__device__ __forceinline__ void cp16(uint32_t dst, const void* src) {
    asm volatile("cp.async.cg.shared.global [%0], [%1], 16;"
                 :: "r"(dst), "l"(src));
}
__device__ __forceinline__ void cp_commit() {
    asm volatile("cp.async.commit_group;");
}
__device__ __forceinline__ void cp_wait0() { asm volatile("cp.async.wait_group 0;"); }
__device__ __forceinline__ void cp_wait1() { asm volatile("cp.async.wait_group 1;"); }

#define LDSM4(d0, d1, d2, d3, addr)                                          \
    asm volatile("ldmatrix.sync.aligned.m8n8.x4.shared.b16 {%0,%1,%2,%3}, [%4];" \
                 : "=r"(d0), "=r"(d1), "=r"(d2), "=r"(d3) : "r"(addr))

#define MMA_TF32(c, a, b)                                                    \
    asm volatile("mma.sync.aligned.m16n8k8.row.col.f32.tf32.tf32.f32 "       \
                 "{%0,%1,%2,%3}, {%4,%5,%6,%7}, {%8,%9}, {%0,%1,%2,%3};"     \
                 : "+f"((c)[0]), "+f"((c)[1]), "+f"((c)[2]), "+f"((c)[3])    \
                 : "r"((a)[0]), "r"((a)[1]), "r"((a)[2]), "r"((a)[3]),       \
                   "r"((b)[0]), "r"((b)[1]))

__device__ __forceinline__ float to_tf32(float v) {
    float r;
    asm("cvt.rna.tf32.f32 %0, %1;" : "=f"(r) : "f"(v));
    return r;
}

__device__ __forceinline__ float gelu_exact(float x) {
    return 0.5f * x * (1.0f + erff(x * 0.70710678118654752f));
}

// ---------------------------------------------------------------------------
// Fused weight transpose (all 4 weights): W[K,N] -> T[N,K], tf32-rounded.
// ---------------------------------------------------------------------------
__global__ void wtrans_all_kernel(const float* __restrict__ Wa,
                                  const float* __restrict__ Wp,
                                  const float* __restrict__ Wf,
                                  const float* __restrict__ Wo,
                                  float* __restrict__ Ta,
                                  float* __restrict__ Tp,
                                  float* __restrict__ Tf,
                                  float* __restrict__ To) {
    const float* W;
    float* T;
    int K, N, lb;
    const int bid = blockIdx.x;
    if (bid < 3072)      { W = Wa; T = Ta; K = DD; N = D3; lb = bid; }
    else if (bid < 4096) { W = Wp; T = Tp; K = DD; N = DD; lb = bid - 3072; }
    else if (bid < 8192) { W = Wf; T = Tf; K = DD; N = D4; lb = bid - 4096; }
    else                 { W = Wo; T = To; K = D4; N = DD; lb = bid - 8192; }
    const int nb = N / 32;
    const int n0 = (lb % nb) * 32;
    const int k0 = (lb / nb) * 32;

    __shared__ float s[32][33];
    const int tx = threadIdx.x, ty = threadIdx.y;
    #pragma unroll
    for (int i = 0; i < 4; i++)
        s[ty + 8 * i][tx] = W[(size_t)(k0 + ty + 8 * i) * N + n0 + tx];
    __syncthreads();
    #pragma unroll
    for (int i = 0; i < 4; i++)
        T[(size_t)(n0 + ty + 8 * i) * K + k0 + tx] = to_tf32(s[tx][ty + 8 * i]);
}

// ---------------------------------------------------------------------------
// LayerNorm -> fp32 tf32-rounded
// ---------------------------------------------------------------------------
__global__ void lnf_kernel(const float* __restrict__ x,
                           const float* __restrict__ g,
                           const float* __restrict__ b,
                           float* __restrict__ o) {
    __shared__ float s_sum[8];
    __shared__ float s_sq[8];
    const int row = blockIdx.x;
    const int tid = threadIdx.x;
    const float4* xr = (const float4*)(x + (size_t)row * DD);
    float4 v = xr[tid];
    float s  = v.x + v.y + v.z + v.w;
    float ss = v.x * v.x + v.y * v.y + v.z * v.z + v.w * v.w;
    #pragma unroll
    for (int off = 16; off > 0; off >>= 1) {
        s  += __shfl_xor_sync(0xffffffffu, s,  off);
        ss += __shfl_xor_sync(0xffffffffu, ss, off);
    }
    if ((tid & 31) == 0) { s_sum[tid >> 5] = s; s_sq[tid >> 5] = ss; }
    __syncthreads();
    float ts = 0.f, tss = 0.f;
    #pragma unroll
    for (int i = 0; i < 8; i++) { ts += s_sum[i]; tss += s_sq[i]; }
    const float mean = ts * (1.0f / DD);
    const float var  = tss * (1.0f / DD) - mean * mean;
    const float rstd = rsqrtf(var + 1e-5f);
    float4 gv = ((const float4*)g)[tid];
    float4 bv = ((const float4*)b)[tid];
    float4 ov;
    ov.x = to_tf32((v.x - mean) * rstd * gv.x + bv.x);
    ov.y = to_tf32((v.y - mean) * rstd * gv.y + bv.y);
    ov.z = to_tf32((v.z - mean) * rstd * gv.z + bv.z);
    ov.w = to_tf32((v.w - mean) * rstd * gv.w + bv.w);
    ((float4*)(o + (size_t)row * DD))[tid] = ov;
}

// ---------------------------------------------------------------------------
// tf32 GEMM: C = A @ B^T. 128x128 tile, 256 threads (8 warps, 4x2),
// K-chunk 32, 3-stage, 2 CTAs/SM, single sync per chunk. (R10 proven config)
// EPI 0: qkv special (q scaled / k -> g_qk ; v -> V^T scatter)
// EPI 1: fp32 + residual   EPI 2: gelu -> tf32 fp32
// ---------------------------------------------------------------------------
#define CHUNK 32
#define TROWB 144
#define TARRB (128 * TROWB)
#define TSTAGEB (2 * TARRB)
#define TNSTAGE 3
#define MMT_SMEM (TNSTAGE * TSTAGEB)   // 110592

template<int EPI>
__global__ void __launch_bounds__(256, 2)
mm_tf32_kernel(const float* __restrict__ A, const float* __restrict__ B,
               const float* __restrict__ R, float* __restrict__ C,
               float* __restrict__ Vt,
               int M, int N, int K) {
    extern __shared__ char smem[];
    const uint32_t sbase = smem_u32(smem);

    const int tid  = threadIdx.x;
    const int lane = tid & 31;
    const int wid  = tid >> 5;
    const int wm   = wid & 3;
    const int wn   = wid >> 2;
    const int row0 = blockIdx.y * 128;
    const int col0 = blockIdx.x * 128;

    const int nch = K >> 5;

    float acc[2][8][4];
    #pragma unroll
    for (int mi = 0; mi < 2; mi++)
        #pragma unroll
        for (int ni = 0; ni < 8; ni++)
            #pragma unroll
            for (int j = 0; j < 4; j++) acc[mi][ni][j] = 0.f;

    const uint32_t a_off = (uint32_t)((wm * 32 + (lane & 15)) * TROWB + ((lane >> 4) << 4));
    const uint32_t b_off = (uint32_t)((wn * 64 + ((lane >> 4) << 3) + (lane & 7)) * TROWB
                                      + (((lane >> 3) & 1) << 4));

#define TISSUE(ch)                                                            \
    do {                                                                      \
        const int k0_ = (ch) * CHUNK;                                         \
        const uint32_t sb_ = sbase + ((ch) % TNSTAGE) * TSTAGEB;              \
        _Pragma("unroll")                                                     \
        for (int t_ = 0; t_ < 4; t_++) {                                      \
            const int idx_ = tid + t_ * 256;                                  \
            const int r_ = idx_ >> 3, c_ = idx_ & 7;                          \
            cp16(sb_ + r_ * TROWB + c_ * 16,                                  \
                 A + (size_t)(row0 + r_) * K + k0_ + c_ * 4);                 \
            cp16(sb_ + TARRB + r_ * TROWB + c_ * 16,                          \
                 B + (size_t)(col0 + r_) * K + k0_ + c_ * 4);                 \
        }                                                                     \
    } while (0)

    TISSUE(0); cp_commit();
    TISSUE(1); cp_commit();

    for (int c = 0; c < nch; c++) {
        cp_wait1();
        __syncthreads();
        if (c + 2 < nch) TISSUE(c + 2);
        cp_commit();

        const uint32_t sb = sbase + (c % TNSTAGE) * TSTAGEB;
        #pragma unroll
        for (int ks = 0; ks < 4; ks++) {
            uint32_t a[2][4];
            #pragma unroll
            for (int mi = 0; mi < 2; mi++)
                LDSM4(a[mi][0], a[mi][1], a[mi][2], a[mi][3],
                      sb + a_off + mi * (16 * TROWB) + ks * 32);
            #pragma unroll
            for (int nb = 0; nb < 4; nb++) {
                uint32_t b0, b1, b2, b3;
                LDSM4(b0, b1, b2, b3,
                      sb + TARRB + b_off + nb * (16 * TROWB) + ks * 32);
                uint32_t bq0[2] = {b0, b1};
                uint32_t bq1[2] = {b2, b3};
                #pragma unroll
                for (int mi = 0; mi < 2; mi++) {
                    MMA_TF32(acc[mi][2 * nb + 0], a[mi], bq0);
                    MMA_TF32(acc[mi][2 * nb + 1], a[mi], bq1);
                }
            }
        }
    }

#undef TISSUE

    const int r_b = row0 + wm * 32 + (lane >> 2);
    const int c_b = col0 + wn * 64 + (lane & 3) * 2;
    #pragma unroll
    for (int mi = 0; mi < 2; mi++) {
        #pragma unroll
        for (int half = 0; half < 2; half++) {
            const size_t r = (size_t)(r_b + mi * 16 + half * 8);
            #pragma unroll
            for (int ni = 0; ni < 8; ni++) {
                const int col = c_b + ni * 8;
                float v0 = acc[mi][ni][half * 2 + 0];
                float v1 = acc[mi][ni][half * 2 + 1];
                if (EPI == 0) {
                    // qkv: q (scaled) | k -> fp32 g_qk ; v -> V^T [b][h][d][tok]
                    if (col0 < 1024) {
                        float2 o;
                        o.x = to_tf32(0.125f * v0);
                        o.y = to_tf32(0.125f * v1);
                        *(float2*)(C + r * 2048 + col) = o;
                    } else if (col0 < 2048) {
                        float2 o;
                        o.x = to_tf32(v0);
                        o.y = to_tf32(v1);
                        *(float2*)(C + r * 2048 + col) = o;
                    } else {
                        const int vc = col - 2048;          // hh*64 + d
                        const size_t vbase = (size_t)(r >> 11) * 1024;
                        const int tok = (int)(r & 2047);
                        Vt[(vbase + vc    ) * 2048 + tok] = to_tf32(v0);
                        Vt[(vbase + vc + 1) * 2048 + tok] = to_tf32(v1);
                    }
                } else if (EPI == 1) {
                    const float2 rv = *(const float2*)(R + r * N + col);
                    float2 o; o.x = v0 + rv.x; o.y = v1 + rv.y;
                    *(float2*)(C + r * N + col) = o;
                } else {
                    float2 o;
                    o.x = to_tf32(gelu_exact(v0));
                    o.y = to_tf32(gelu_exact(v1));
                    *(float2*)(C + r * N + col) = o;
                }
            }
        }
    }
}

// ---------------------------------------------------------------------------
// Causal flash attention, all tf32. 128 threads, 3 CTAs/SM.
// Q pre-scaled by 0.125. P -> A-frags via quad shuffles (validated R12).
// V^T in smem ([d][token], pitch 272) -> B-frags via LDSM, same path as K.
// ---------------------------------------------------------------------------
#define KROWB 272
#define KARR  (64 * KROWB)             // 17408
#define VTROWB 272
#define VTARR (64 * VTROWB)            // 17408
#define ASTG  (KARR + VTARR)           // 34816
#define ATT_SMEM (2 * ASTG)            // 69632

__global__ void __launch_bounds__(128, 3)
attn_kernel(const float* __restrict__ qk,
            const float* __restrict__ vtg,
            float* __restrict__ y) {
    extern __shared__ char asmem[];
    const uint32_t sb = smem_u32(asmem);

    const int qt = (int)gridDim.x - 1 - (int)blockIdx.x;
    const int bh = blockIdx.y;
    const int bb = bh >> 4;
    const int hh = bh & 15;

    const int tid  = threadIdx.x;
    const int lane = tid & 31;
    const int w    = tid >> 5;

    const float* qptr  = qk + (size_t)bb * TT * 2048 + hh * HDIM;
    const float* kptr  = qk + (size_t)bb * TT * 2048 + 1024 + hh * HDIM;
    const float* vtptr = vtg + ((size_t)bb * 1024 + hh * 64) * 2048;

    const int nkt = qt + 1;

#define ALOADK(dst, src, trow)                                                \
    do {                                                                      \
        _Pragma("unroll")                                                     \
        for (int i_ = 0; i_ < 8; i_++) {                                      \
            const int idx_ = tid + i_ * 128;                                  \
            const int r_ = idx_ >> 4, c_ = idx_ & 15;                         \
            cp16((dst) + r_ * KROWB + c_ * 16,                                \
                 (src) + (size_t)((trow) + r_) * 2048 + c_ * 4);              \
        }                                                                     \
    } while (0)

    // V^T tile: 64 d-rows x 64 tokens; row r_ = d, cols = token segment
#define ALOADVT(dst, src, tcol)                                               \
    do {                                                                      \
        _Pragma("unroll")                                                     \
        for (int i_ = 0; i_ < 8; i_++) {                                      \
            const int idx_ = tid + i_ * 128;                                  \
            const int r_ = idx_ >> 4, c_ = idx_ & 15;                         \
            cp16((dst) + r_ * VTROWB + c_ * 16,                               \
                 (src) + (size_t)r_ * 2048 + (tcol) + c_ * 4);                \
        }                                                                     \
    } while (0)

#define AKV(kt_)                                                              \
    do {                                                                      \
        const uint32_t st_ = sb + ((kt_) & 1) * ASTG;                         \
        ALOADK(st_, kptr, (kt_) * 64);                                        \
        ALOADVT(st_ + KARR, vtptr, (kt_) * 64);                               \
    } while (0)

    ALOADK(sb, qptr, qt * 64);
    cp_commit();
    cp_wait0();
    __syncthreads();

    uint32_t qf[8][4];
    {
        const uint32_t qa = (uint32_t)((w * 16 + (lane & 15)) * KROWB + ((lane >> 4) << 4));
        #pragma unroll
        for (int ks = 0; ks < 8; ks++)
            LDSM4(qf[ks][0], qf[ks][1], qf[ks][2], qf[ks][3], sb + qa + ks * 32);
    }
    __syncthreads();

    AKV(0);
    cp_commit();
    if (nkt > 1) AKV(1);
    cp_commit();
    cp_wait1();
    __syncthreads();

    float o[8][4];
    #pragma unroll
    for (int nb = 0; nb < 8; nb++)
        #pragma unroll
        for (int j = 0; j < 4; j++) o[nb][j] = 0.f;
    float m0 = -INFINITY, m1 = -INFINITY, l0 = 0.f, l1 = 0.f;

    const uint32_t kb_off = (uint32_t)((((lane >> 4) << 3) + (lane & 7)) * KROWB
                                       + (((lane >> 3) & 1) << 4));
    const uint32_t vb_off = (uint32_t)((((lane >> 4) << 3) + (lane & 7)) * VTROWB
                                       + (((lane >> 3) & 1) << 4));

    // P C-frag -> tf32 A-frag shuffle owners (within quad)
    const int o1 = (lane & 0x1C) | ((lane & 3) >> 1);
    const int o2 = o1 + 2;
    const bool oddk = (lane & 1);

    for (int kt = 0; kt < nkt; kt++) {
        const uint32_t stg = sb + (kt & 1) * ASTG;

        // ---- S = Q K^T (tf32; Q pre-scaled) ----
        float s[8][4];
        #pragma unroll
        for (int nb = 0; nb < 8; nb++)
            #pragma unroll
            for (int j = 0; j < 4; j++) s[nb][j] = 0.f;

        #pragma unroll
        for (int ks = 0; ks < 8; ks++) {
            #pragma unroll
            for (int nb2 = 0; nb2 < 4; nb2++) {
                uint32_t b0, b1, b2, b3;
                LDSM4(b0, b1, b2, b3,
                      stg + kb_off + nb2 * (16 * KROWB) + ks * 32);
                uint32_t bq0[2] = {b0, b1};
                uint32_t bq1[2] = {b2, b3};
                MMA_TF32(s[2 * nb2 + 0], qf[ks], bq0);
                MMA_TF32(s[2 * nb2 + 1], qf[ks], bq1);
            }
        }

        if (kt == qt) {
            const int r0 = w * 16 + (lane >> 2);
            #pragma unroll
            for (int nb = 0; nb < 8; nb++) {
                const int c0 = nb * 8 + (lane & 3) * 2;
                if (c0     > r0)     s[nb][0] = -1e30f;
                if (c0 + 1 > r0)     s[nb][1] = -1e30f;
                if (c0     > r0 + 8) s[nb][2] = -1e30f;
                if (c0 + 1 > r0 + 8) s[nb][3] = -1e30f;
            }
        }

        // ---- online softmax (p rounded to tf32 BEFORE row sum) ----
        float mx0 = -INFINITY, mx1 = -INFINITY;
        #pragma unroll
        for (int nb = 0; nb < 8; nb++) {
            mx0 = fmaxf(mx0, fmaxf(s[nb][0], s[nb][1]));
            mx1 = fmaxf(mx1, fmaxf(s[nb][2], s[nb][3]));
        }
        mx0 = fmaxf(mx0, __shfl_xor_sync(0xffffffffu, mx0, 1));
        mx0 = fmaxf(mx0, __shfl_xor_sync(0xffffffffu, mx0, 2));
        mx1 = fmaxf(mx1, __shfl_xor_sync(0xffffffffu, mx1, 1));
        mx1 = fmaxf(mx1, __shfl_xor_sync(0xffffffffu, mx1, 2));

        const float mn0 = fmaxf(m0, mx0);
        const float mn1 = fmaxf(m1, mx1);
        const float al0 = __expf(m0 - mn0);
        const float al1 = __expf(m1 - mn1);
        m0 = mn0; m1 = mn1;

        float ls0 = 0.f, ls1 = 0.f;
        #pragma unroll
        for (int nb = 0; nb < 8; nb++) {
            s[nb][0] = to_tf32(__expf(s[nb][0] - mn0));
            s[nb][1] = to_tf32(__expf(s[nb][1] - mn0));
            s[nb][2] = to_tf32(__expf(s[nb][2] - mn1));
            s[nb][3] = to_tf32(__expf(s[nb][3] - mn1));
            ls0 += s[nb][0] + s[nb][1];
            ls1 += s[nb][2] + s[nb][3];
        }
        ls0 += __shfl_xor_sync(0xffffffffu, ls0, 1);
        ls0 += __shfl_xor_sync(0xffffffffu, ls0, 2);
        ls1 += __shfl_xor_sync(0xffffffffu, ls1, 1);
        ls1 += __shfl_xor_sync(0xffffffffu, ls1, 2);
        l0 = l0 * al0 + ls0;
        l1 = l1 * al1 + ls1;

        #pragma unroll
        for (int nb = 0; nb < 8; nb++) {
            o[nb][0] *= al0; o[nb][1] *= al0;
            o[nb][2] *= al1; o[nb][3] *= al1;
        }

        // ---- O += P V (tf32): A via shuffles, B via LDSM on V^T ----
        const uint32_t vbase = stg + KARR + vb_off;
        #pragma unroll
        for (int g = 0; g < 8; g++) {
            float t0a = __shfl_sync(0xffffffffu, s[g][0], o1);
            float t1a = __shfl_sync(0xffffffffu, s[g][1], o1);
            float t2a = __shfl_sync(0xffffffffu, s[g][2], o1);
            float t3a = __shfl_sync(0xffffffffu, s[g][3], o1);
            float t0b = __shfl_sync(0xffffffffu, s[g][0], o2);
            float t1b = __shfl_sync(0xffffffffu, s[g][1], o2);
            float t2b = __shfl_sync(0xffffffffu, s[g][2], o2);
            float t3b = __shfl_sync(0xffffffffu, s[g][3], o2);
            uint32_t a[4];
            a[0] = __float_as_uint(oddk ? t1a : t0a);
            a[1] = __float_as_uint(oddk ? t3a : t2a);
            a[2] = __float_as_uint(oddk ? t1b : t0b);
            a[3] = __float_as_uint(oddk ? t3b : t2b);

            #pragma unroll
            for (int nb2 = 0; nb2 < 4; nb2++) {
                uint32_t b0, b1, b2, b3;
                LDSM4(b0, b1, b2, b3,
                      vbase + nb2 * (16 * VTROWB) + g * 32);
                uint32_t bq0[2] = {b0, b1};
                uint32_t bq1[2] = {b2, b3};
                MMA_TF32(o[2 * nb2 + 0], a, bq0);
                MMA_TF32(o[2 * nb2 + 1], a, bq1);
            }
        }

        __syncthreads();
        if (kt + 2 < nkt) AKV(kt + 2);
        cp_commit();
        cp_wait1();
        __syncthreads();
    }

#undef AKV
#undef ALOADVT
#undef ALOADK

    const float inv0 = 1.0f / l0;
    const float inv1 = 1.0f / l1;
    const int rr0 = qt * 64 + w * 16 + (lane >> 2);
    #pragma unroll
    for (int nb = 0; nb < 8; nb++) {
        const int col = hh * HDIM + nb * 8 + (lane & 3) * 2;
        const size_t t0 = (size_t)(bb * TT + rr0) * DD + col;
        const size_t t1 = (size_t)(bb * TT + rr0 + 8) * DD + col;
        float2 y0, y1;
        y0.x = to_tf32(o[nb][0] * inv0);
        y0.y = to_tf32(o[nb][1] * inv0);
        y1.x = to_tf32(o[nb][2] * inv1);
        y1.y = to_tf32(o[nb][3] * inv1);
        *(float2*)(y + t0) = y0;
        *(float2*)(y + t1) = y1;
    }
}

// ---------------------------------------------------------------------------
extern "C" void kernel_launch(void* const* d_in, const int* in_sizes, int n_in,
                              void* d_out, int out_size) {
    const float* x      = (const float*)d_in[0];
    const float* w_attn = (const float*)d_in[1];
    const float* w_proj = (const float*)d_in[2];
    const float* w_fc   = (const float*)d_in[3];
    const float* w_out  = (const float*)d_in[4];
    const float* ln1_g  = (const float*)d_in[5];
    const float* ln1_b  = (const float*)d_in[6];
    const float* ln2_g  = (const float*)d_in[7];
    const float* ln2_b  = (const float*)d_in[8];
    float* out = (float*)d_out;

    float *p_x2, *p_y, *p_xnf, *p_fcf, *p_qk, *p_vt;
    float *p_waf, *p_wpf, *p_wff, *p_wof;
    cudaGetSymbolAddress((void**)&p_x2,  g_x2);
    cudaGetSymbolAddress((void**)&p_y,   g_y);
    cudaGetSymbolAddress((void**)&p_xnf, g_xnf);
    cudaGetSymbolAddress((void**)&p_fcf, g_fcf);
    cudaGetSymbolAddress((void**)&p_qk,  g_qk);
    cudaGetSymbolAddress((void**)&p_vt,  g_vt);
    cudaGetSymbolAddress((void**)&p_waf, g_wattnf);
    cudaGetSymbolAddress((void**)&p_wpf, g_wprojf);
    cudaGetSymbolAddress((void**)&p_wff, g_wfcf);
    cudaGetSymbolAddress((void**)&p_wof, g_woutf);

    cudaFuncSetAttribute(attn_kernel,
                         cudaFuncAttributeMaxDynamicSharedMemorySize, ATT_SMEM);
    cudaFuncSetAttribute(mm_tf32_kernel<0>,
                         cudaFuncAttributeMaxDynamicSharedMemorySize, MMT_SMEM);
    cudaFuncSetAttribute(mm_tf32_kernel<1>,
                         cudaFuncAttributeMaxDynamicSharedMemorySize, MMT_SMEM);
    cudaFuncSetAttribute(mm_tf32_kernel<2>,
                         cudaFuncAttributeMaxDynamicSharedMemorySize, MMT_SMEM);

    // weight prep (single fused launch, all tf32)
    wtrans_all_kernel<<<12288, dim3(32, 8)>>>(w_attn, w_proj, w_fc, w_out,
                                              p_waf, p_wpf, p_wff, p_wof);

    // 1) ln1 -> tf32 fp32
    lnf_kernel<<<ROWS, 256>>>(x, ln1_g, ln1_b, p_xnf);

    // 2) qkv = xn @ w_attn (tf32; q scaled / k fp32 / v -> V^T)
    mm_tf32_kernel<0><<<dim3(D3 / 128, ROWS / 128), 256, MMT_SMEM>>>(
        p_xnf, p_waf, nullptr, p_qk, p_vt, ROWS, D3, DD);

    // 3) y = causal MHA
    attn_kernel<<<dim3(TT / 64, BB * HH), 128, ATT_SMEM>>>(p_qk, p_vt, p_y);

    // 4) x2 = x + y @ w_proj
    mm_tf32_kernel<1><<<dim3(DD / 128, ROWS / 128), 256, MMT_SMEM>>>(
        p_y, p_wpf, x, p_x2, nullptr, ROWS, DD, DD);

    // 5) ln2 -> tf32 fp32
    lnf_kernel<<<ROWS, 256>>>(p_x2, ln2_g, ln2_b, p_xnf);

    // 6) fc = gelu(xn @ w_fc)
    mm_tf32_kernel<2><<<dim3(D4 / 128, ROWS / 128), 256, MMT_SMEM>>>(
        p_xnf, p_wff, nullptr, p_fcf, nullptr, ROWS, D4, DD);

    // 7) out = x2 + fc @ w_out
    mm_tf32_kernel<1><<<dim3(DD / 128, ROWS / 128), 256, MMT_SMEM>>>(
        p_fcf, p_wof, p_x2, out, nullptr, ROWS, DD, D4);
}

// round 15
// speedup vs baseline: 1.5400x; 1.5400x over previous
#include <cuda_runtime.h>
#include <cuda_bf16.h>
#include <math.h>
#include <stdint.h>

#define BB 2
#define TT 2048
#define DD 1024
#define HH 16
#define HDIM 64
#define ROWS (BB * TT)
#define D3 (3 * DD)
#define D4 (4 * DD)

// fp32 scratch
__device__ float g_x2 [ROWS * DD];
__device__ float g_y  [ROWS * DD];       // attention out (tf32-rounded)
__device__ float g_xnf[ROWS * DD];       // ln out (tf32-rounded, reused)
__device__ float g_fcf[ROWS * D4];       // gelu out (tf32-rounded)
__device__ float g_qk [ROWS * 2 * DD];   // [q(scaled)|k] fp32 tf32-rounded
__device__ float g_wattnf[D3 * DD];      // transposed tf32 weights [N,K]
__device__ float g_wprojf[DD * DD];
__device__ float g_wfcf [D4 * DD];
__device__ float g_woutf[DD * D4];

// bf16 split V (for attention PV)
__device__ __nv_bfloat16 g_vh[ROWS * DD], g_vl[ROWS * DD];

__device__ __forceinline__ uint32_t smem_u32(const void* p) {
    uint32_t a;
    asm("{ .reg .u64 t; cvta.to.shared.u64 t, %1; cvt.u32.u64 %0, t; }"
        : "=r"(a) : "l"(p));
    return a;
}

__device__ __forceinline__ void cp16(uint32_t dst, const void* src) {
    asm volatile("cp.async.cg.shared.global [%0], [%1], 16;"
                 :: "r"(dst), "l"(src));
}
__device__ __forceinline__ void cp_commit() {
    asm volatile("cp.async.commit_group;");
}
__device__ __forceinline__ void cp_wait0() { asm volatile("cp.async.wait_group 0;"); }
__device__ __forceinline__ void cp_wait1() { asm volatile("cp.async.wait_group 1;"); }

#define LDSM4(d0, d1, d2, d3, addr)                                          \
    asm volatile("ldmatrix.sync.aligned.m8n8.x4.shared.b16 {%0,%1,%2,%3}, [%4];" \
                 : "=r"(d0), "=r"(d1), "=r"(d2), "=r"(d3) : "r"(addr))

#define LDSM4T(d0, d1, d2, d3, addr)                                         \
    asm volatile("ldmatrix.sync.aligned.m8n8.x4.trans.shared.b16 {%0,%1,%2,%3}, [%4];" \
                 : "=r"(d0), "=r"(d1), "=r"(d2), "=r"(d3) : "r"(addr))

#define MMA_BF16(c, a, b)                                                    \
    asm volatile("mma.sync.aligned.m16n8k16.row.col.f32.bf16.bf16.f32 "      \
                 "{%0,%1,%2,%3}, {%4,%5,%6,%7}, {%8,%9}, {%0,%1,%2,%3};"     \
                 : "+f"((c)[0]), "+f"((c)[1]), "+f"((c)[2]), "+f"((c)[3])    \
                 : "r"((a)[0]), "r"((a)[1]), "r"((a)[2]), "r"((a)[3]),       \
                   "r"((b)[0]), "r"((b)[1]))

#define MMA_TF32(c, a, b)                                                    \
    asm volatile("mma.sync.aligned.m16n8k8.row.col.f32.tf32.tf32.f32 "       \
                 "{%0,%1,%2,%3}, {%4,%5,%6,%7}, {%8,%9}, {%0,%1,%2,%3};"     \
                 : "+f"((c)[0]), "+f"((c)[1]), "+f"((c)[2]), "+f"((c)[3])    \
                 : "r"((a)[0]), "r"((a)[1]), "r"((a)[2]), "r"((a)[3]),       \
                   "r"((b)[0]), "r"((b)[1]))

__device__ __forceinline__ float to_tf32(float v) {
    float r;
    asm("cvt.rna.tf32.f32 %0, %1;" : "=f"(r) : "f"(v));
    return r;
}

__device__ __forceinline__ void split_bf16(float v, __nv_bfloat16& h, __nv_bfloat16& l) {
    h = __float2bfloat16(v);
    l = __float2bfloat16(v - __bfloat162float(h));
}

__device__ __forceinline__ uint32_t pack_bf16(__nv_bfloat16 a, __nv_bfloat16 b) {
    __nv_bfloat162 v; v.x = a; v.y = b;
    return *reinterpret_cast<uint32_t*>(&v);
}

__device__ __forceinline__ float gelu_exact(float x) {
    return 0.5f * x * (1.0f + erff(x * 0.70710678118654752f));
}

// ---------------------------------------------------------------------------
// Fused weight transpose (all 4 weights): W[K,N] -> T[N,K], tf32-rounded.
// ---------------------------------------------------------------------------
__global__ void wtrans_all_kernel(const float* __restrict__ Wa,
                                  const float* __restrict__ Wp,
                                  const float* __restrict__ Wf,
                                  const float* __restrict__ Wo,
                                  float* __restrict__ Ta,
                                  float* __restrict__ Tp,
                                  float* __restrict__ Tf,
                                  float* __restrict__ To) {
    const float* W;
    float* T;
    int K, N, lb;
    const int bid = blockIdx.x;
    if (bid < 3072)      { W = Wa; T = Ta; K = DD; N = D3; lb = bid; }
    else if (bid < 4096) { W = Wp; T = Tp; K = DD; N = DD; lb = bid - 3072; }
    else if (bid < 8192) { W = Wf; T = Tf; K = DD; N = D4; lb = bid - 4096; }
    else                 { W = Wo; T = To; K = D4; N = DD; lb = bid - 8192; }
    const int nb = N / 32;
    const int n0 = (lb % nb) * 32;
    const int k0 = (lb / nb) * 32;

    __shared__ float s[32][33];
    const int tx = threadIdx.x, ty = threadIdx.y;
    #pragma unroll
    for (int i = 0; i < 4; i++)
        s[ty + 8 * i][tx] = W[(size_t)(k0 + ty + 8 * i) * N + n0 + tx];
    __syncthreads();
    #pragma unroll
    for (int i = 0; i < 4; i++)
        T[(size_t)(n0 + ty + 8 * i) * K + k0 + tx] = to_tf32(s[tx][ty + 8 * i]);
}

// ---------------------------------------------------------------------------
// LayerNorm -> fp32 tf32-rounded
// ---------------------------------------------------------------------------
__global__ void lnf_kernel(const float* __restrict__ x,
                           const float* __restrict__ g,
                           const float* __restrict__ b,
                           float* __restrict__ o) {
    __shared__ float s_sum[8];
    __shared__ float s_sq[8];
    const int row = blockIdx.x;
    const int tid = threadIdx.x;
    const float4* xr = (const float4*)(x + (size_t)row * DD);
    float4 v = xr[tid];
    float s  = v.x + v.y + v.z + v.w;
    float ss = v.x * v.x + v.y * v.y + v.z * v.z + v.w * v.w;
    #pragma unroll
    for (int off = 16; off > 0; off >>= 1) {
        s  += __shfl_xor_sync(0xffffffffu, s,  off);
        ss += __shfl_xor_sync(0xffffffffu, ss, off);
    }
    if ((tid & 31) == 0) { s_sum[tid >> 5] = s; s_sq[tid >> 5] = ss; }
    __syncthreads();
    float ts = 0.f, tss = 0.f;
    #pragma unroll
    for (int i = 0; i < 8; i++) { ts += s_sum[i]; tss += s_sq[i]; }
    const float mean = ts * (1.0f / DD);
    const float var  = tss * (1.0f / DD) - mean * mean;
    const float rstd = rsqrtf(var + 1e-5f);
    float4 gv = ((const float4*)g)[tid];
    float4 bv = ((const float4*)b)[tid];
    float4 ov;
    ov.x = to_tf32((v.x - mean) * rstd * gv.x + bv.x);
    ov.y = to_tf32((v.y - mean) * rstd * gv.y + bv.y);
    ov.z = to_tf32((v.z - mean) * rstd * gv.z + bv.z);
    ov.w = to_tf32((v.w - mean) * rstd * gv.w + bv.w);
    ((float4*)(o + (size_t)row * DD))[tid] = ov;
}

// ---------------------------------------------------------------------------
// tf32 GEMM: C = A @ B^T. 128x128 tile, K-chunk 32, 3-stage, 2 CTAs/SM.
// Single __syncthreads per chunk: [wait1, sync, issue(c+2), compute].
// EPI 0: qkv special   EPI 1: fp32 + residual   EPI 2: gelu -> tf32 fp32
// ---------------------------------------------------------------------------
#define CHUNK 32
#define TROWB 144
#define TARRB (128 * TROWB)
#define TSTAGEB (2 * TARRB)
#define TNSTAGE 3
#define MMT_SMEM (TNSTAGE * TSTAGEB)   // 110592

template<int EPI>
__global__ void __launch_bounds__(256, 2)
mm_tf32_kernel(const float* __restrict__ A, const float* __restrict__ B,
               const float* __restrict__ R, float* __restrict__ C,
               __nv_bfloat16* __restrict__ Vh, __nv_bfloat16* __restrict__ Vl,
               int M, int N, int K) {
    extern __shared__ char smem[];
    const uint32_t sbase = smem_u32(smem);

    const int tid  = threadIdx.x;
    const int lane = tid & 31;
    const int wid  = tid >> 5;
    const int wm   = wid & 3;
    const int wn   = wid >> 2;
    const int row0 = blockIdx.y * 128;
    const int col0 = blockIdx.x * 128;

    const int nch = K >> 5;

    float acc[2][8][4];
    #pragma unroll
    for (int mi = 0; mi < 2; mi++)
        #pragma unroll
        for (int ni = 0; ni < 8; ni++)
            #pragma unroll
            for (int j = 0; j < 4; j++) acc[mi][ni][j] = 0.f;

    const uint32_t a_off = (uint32_t)((wm * 32 + (lane & 15)) * TROWB + ((lane >> 4) << 4));
    const uint32_t b_off = (uint32_t)((wn * 64 + ((lane >> 4) << 3) + (lane & 7)) * TROWB
                                      + (((lane >> 3) & 1) << 4));

#define TISSUE(ch)                                                            \
    do {                                                                      \
        const int k0_ = (ch) * CHUNK;                                         \
        const uint32_t sb_ = sbase + ((ch) % TNSTAGE) * TSTAGEB;              \
        _Pragma("unroll")                                                     \
        for (int t_ = 0; t_ < 4; t_++) {                                      \
            const int idx_ = tid + t_ * 256;                                  \
            const int r_ = idx_ >> 3, c_ = idx_ & 7;                          \
            cp16(sb_ + r_ * TROWB + c_ * 16,                                  \
                 A + (size_t)(row0 + r_) * K + k0_ + c_ * 4);                 \
            cp16(sb_ + TARRB + r_ * TROWB + c_ * 16,                          \
                 B + (size_t)(col0 + r_) * K + k0_ + c_ * 4);                 \
        }                                                                     \
    } while (0)

    TISSUE(0); cp_commit();
    TISSUE(1); cp_commit();

    for (int c = 0; c < nch; c++) {
        cp_wait1();
        __syncthreads();
        if (c + 2 < nch) TISSUE(c + 2);
        cp_commit();

        const uint32_t sb = sbase + (c % TNSTAGE) * TSTAGEB;
        #pragma unroll
        for (int ks = 0; ks < 4; ks++) {
            uint32_t a[2][4];
            #pragma unroll
            for (int mi = 0; mi < 2; mi++)
                LDSM4(a[mi][0], a[mi][1], a[mi][2], a[mi][3],
                      sb + a_off + mi * (16 * TROWB) + ks * 32);
            #pragma unroll
            for (int nb = 0; nb < 4; nb++) {
                uint32_t b0, b1, b2, b3;
                LDSM4(b0, b1, b2, b3,
                      sb + TARRB + b_off + nb * (16 * TROWB) + ks * 32);
                uint32_t bq0[2] = {b0, b1};
                uint32_t bq1[2] = {b2, b3};
                #pragma unroll
                for (int mi = 0; mi < 2; mi++) {
                    MMA_TF32(acc[mi][2 * nb + 0], a[mi], bq0);
                    MMA_TF32(acc[mi][2 * nb + 1], a[mi], bq1);
                }
            }
        }
    }

#undef TISSUE

    const int r_b = row0 + wm * 32 + (lane >> 2);
    const int c_b = col0 + wn * 64 + (lane & 3) * 2;
    #pragma unroll
    for (int mi = 0; mi < 2; mi++) {
        #pragma unroll
        for (int half = 0; half < 2; half++) {
            const size_t r = (size_t)(r_b + mi * 16 + half * 8);
            #pragma unroll
            for (int ni = 0; ni < 8; ni++) {
                const int col = c_b + ni * 8;
                float v0 = acc[mi][ni][half * 2 + 0];
                float v1 = acc[mi][ni][half * 2 + 1];
                if (EPI == 0) {
                    // qkv: q (scaled) | k -> fp32 g_qk ; v -> bf16 hi/lo
                    if (col0 < 1024) {
                        float2 o;
                        o.x = to_tf32(0.125f * v0);
                        o.y = to_tf32(0.125f * v1);
                        *(float2*)(C + r * 2048 + col) = o;
                    } else if (col0 < 2048) {
                        float2 o;
                        o.x = to_tf32(v0);
                        o.y = to_tf32(v1);
                        *(float2*)(C + r * 2048 + col) = o;
                    } else {
                        const int vc = col - 2048;
                        __nv_bfloat16 h0, l0, h1, l1;
                        split_bf16(v0, h0, l0);
                        split_bf16(v1, h1, l1);
                        *(uint32_t*)(Vh + r * DD + vc) = pack_bf16(h0, h1);
                        *(uint32_t*)(Vl + r * DD + vc) = pack_bf16(l0, l1);
                    }
                } else if (EPI == 1) {
                    const float2 rv = *(const float2*)(R + r * N + col);
                    float2 o; o.x = v0 + rv.x; o.y = v1 + rv.y;
                    *(float2*)(C + r * N + col) = o;
                } else {
                    float2 o;
                    o.x = to_tf32(gelu_exact(v0));
                    o.y = to_tf32(gelu_exact(v1));
                    *(float2*)(C + r * N + col) = o;
                }
            }
        }
    }
}

// ---------------------------------------------------------------------------
// Causal flash attention: S via tf32 (fp32 Q/K), PV via bf16 3-term (V hi/lo).
// 128 threads, 3 CTAs/SM. Q pre-scaled by 0.125 in qkv epilogue.
// ---------------------------------------------------------------------------
#define KROWB 272                      // 64 fp32 + pad (16-aligned, conflict-free)
#define KARR  (64 * KROWB)             // 17408
#define VROWB 144
#define VARR  (64 * VROWB)             // 9216
#define ASTG  (KARR + 2 * VARR)        // 35840
#define ATT_SMEM (2 * ASTG)            // 71680

__global__ void __launch_bounds__(128, 3)
attn_kernel(const float* __restrict__ qk,
            const __nv_bfloat16* __restrict__ vhg,
            const __nv_bfloat16* __restrict__ vlg,
            float* __restrict__ y) {
    extern __shared__ char asmem[];
    const uint32_t sb = smem_u32(asmem);

    const int qt = (int)gridDim.x - 1 - (int)blockIdx.x;
    const int bh = blockIdx.y;
    const int bb = bh >> 4;
    const int hh = bh & 15;

    const int tid  = threadIdx.x;
    const int lane = tid & 31;
    const int w    = tid >> 5;

    const float* qptr = qk + (size_t)bb * TT * 2048 + hh * HDIM;
    const float* kptr = qk + (size_t)bb * TT * 2048 + 1024 + hh * HDIM;
    const __nv_bfloat16* vh = vhg + (size_t)bb * TT * DD + hh * HDIM;
    const __nv_bfloat16* vl = vlg + (size_t)bb * TT * DD + hh * HDIM;

    const int nkt = qt + 1;

#define ALOADF(dst, src, trow)                                                \
    do {                                                                      \
        _Pragma("unroll")                                                     \
        for (int i_ = 0; i_ < 8; i_++) {                                      \
            const int idx_ = tid + i_ * 128;                                  \
            const int r_ = idx_ >> 4, c_ = idx_ & 15;                         \
            cp16((dst) + r_ * KROWB + c_ * 16,                                \
                 (src) + (size_t)((trow) + r_) * 2048 + c_ * 4);              \
        }                                                                     \
    } while (0)

#define ALOADV(dst, src, trow)                                                \
    do {                                                                      \
        _Pragma("unroll")                                                     \
        for (int i_ = 0; i_ < 4; i_++) {                                      \
            const int idx_ = tid + i_ * 128;                                  \
            const int r_ = idx_ >> 3, c_ = idx_ & 7;                          \
            cp16((dst) + r_ * VROWB + c_ * 16,                                \
                 (src) + (size_t)((trow) + r_) * DD + c_ * 8);                \
        }                                                                     \
    } while (0)

#define AKV(kt_)                                                              \
    do {                                                                      \
        const uint32_t st_ = sb + ((kt_) & 1) * ASTG;                         \
        ALOADF(st_, kptr, (kt_) * 64);                                        \
        ALOADV(st_ + KARR, vh, (kt_) * 64);                                   \
        ALOADV(st_ + KARR + VARR, vl, (kt_) * 64);                            \
    } while (0)

    ALOADF(sb, qptr, qt * 64);
    cp_commit();
    cp_wait0();
    __syncthreads();

    uint32_t qf[8][4];
    {
        const uint32_t qa = (uint32_t)((w * 16 + (lane & 15)) * KROWB + ((lane >> 4) << 4));
        #pragma unroll
        for (int ks = 0; ks < 8; ks++)
            LDSM4(qf[ks][0], qf[ks][1], qf[ks][2], qf[ks][3], sb + qa + ks * 32);
    }
    __syncthreads();

    AKV(0);
    cp_commit();
    if (nkt > 1) AKV(1);
    cp_commit();
    cp_wait1();
    __syncthreads();

    float o[8][4];
    #pragma unroll
    for (int nb = 0; nb < 8; nb++)
        #pragma unroll
        for (int j = 0; j < 4; j++) o[nb][j] = 0.f;
    float m0 = -INFINITY, m1 = -INFINITY, l0 = 0.f, l1 = 0.f;

    const uint32_t kb_off = (uint32_t)((((lane >> 4) << 3) + (lane & 7)) * KROWB
                                       + (((lane >> 3) & 1) << 4));
    const uint32_t vb_off = (uint32_t)(((((lane >> 3) & 1) << 3) + (lane & 7)) * VROWB
                                       + ((lane >> 4) << 4));

    for (int kt = 0; kt < nkt; kt++) {
        const uint32_t stg = sb + (kt & 1) * ASTG;

        float s[8][4];
        #pragma unroll
        for (int nb = 0; nb < 8; nb++)
            #pragma unroll
            for (int j = 0; j < 4; j++) s[nb][j] = 0.f;

        #pragma unroll
        for (int ks = 0; ks < 8; ks++) {
            #pragma unroll
            for (int nb2 = 0; nb2 < 4; nb2++) {
                uint32_t b0, b1, b2, b3;
                LDSM4(b0, b1, b2, b3,
                      stg + kb_off + nb2 * (16 * KROWB) + ks * 32);
                uint32_t bq0[2] = {b0, b1};
                uint32_t bq1[2] = {b2, b3};
                MMA_TF32(s[2 * nb2 + 0], qf[ks], bq0);
                MMA_TF32(s[2 * nb2 + 1], qf[ks], bq1);
            }
        }

        if (kt == qt) {
            const int r0 = w * 16 + (lane >> 2);
            #pragma unroll
            for (int nb = 0; nb < 8; nb++) {
                const int c0 = nb * 8 + (lane & 3) * 2;
                if (c0     > r0)     s[nb][0] = -1e30f;
                if (c0 + 1 > r0)     s[nb][1] = -1e30f;
                if (c0     > r0 + 8) s[nb][2] = -1e30f;
                if (c0 + 1 > r0 + 8) s[nb][3] = -1e30f;
            }
        }

        float mx0 = -INFINITY, mx1 = -INFINITY;
        #pragma unroll
        for (int nb = 0; nb < 8; nb++) {
            mx0 = fmaxf(mx0, fmaxf(s[nb][0], s[nb][1]));
            mx1 = fmaxf(mx1, fmaxf(s[nb][2], s[nb][3]));
        }
        mx0 = fmaxf(mx0, __shfl_xor_sync(0xffffffffu, mx0, 1));
        mx0 = fmaxf(mx0, __shfl_xor_sync(0xffffffffu, mx0, 2));
        mx1 = fmaxf(mx1, __shfl_xor_sync(0xffffffffu, mx1, 1));
        mx1 = fmaxf(mx1, __shfl_xor_sync(0xffffffffu, mx1, 2));

        const float mn0 = fmaxf(m0, mx0);
        const float mn1 = fmaxf(m1, mx1);
        const float al0 = __expf(m0 - mn0);
        const float al1 = __expf(m1 - mn1);
        m0 = mn0; m1 = mn1;

        float ls0 = 0.f, ls1 = 0.f;
        #pragma unroll
        for (int nb = 0; nb < 8; nb++) {
            s[nb][0] = __expf(s[nb][0] - mn0);
            s[nb][1] = __expf(s[nb][1] - mn0);
            s[nb][2] = __expf(s[nb][2] - mn1);
            s[nb][3] = __expf(s[nb][3] - mn1);
            ls0 += s[nb][0] + s[nb][1];
            ls1 += s[nb][2] + s[nb][3];
        }
        ls0 += __shfl_xor_sync(0xffffffffu, ls0, 1);
        ls0 += __shfl_xor_sync(0xffffffffu, ls0, 2);
        ls1 += __shfl_xor_sync(0xffffffffu, ls1, 1);
        ls1 += __shfl_xor_sync(0xffffffffu, ls1, 2);
        l0 = l0 * al0 + ls0;
        l1 = l1 * al1 + ls1;

        #pragma unroll
        for (int nb = 0; nb < 8; nb++) {
            o[nb][0] *= al0; o[nb][1] *= al0;
            o[nb][2] *= al1; o[nb][3] *= al1;
        }

        uint32_t pfh[4][4], pfl[4][4];
        #pragma unroll
        for (int t = 0; t < 4; t++) {
            __nv_bfloat16 h[8], lo_[8];
            #pragma unroll
            for (int j = 0; j < 4; j++) {
                split_bf16(s[2*t][j],   h[j],     lo_[j]);
                split_bf16(s[2*t+1][j], h[4 + j], lo_[4 + j]);
            }
            pfh[t][0] = pack_bf16(h[0], h[1]);
            pfh[t][1] = pack_bf16(h[2], h[3]);
            pfh[t][2] = pack_bf16(h[4], h[5]);
            pfh[t][3] = pack_bf16(h[6], h[7]);
            pfl[t][0] = pack_bf16(lo_[0], lo_[1]);
            pfl[t][1] = pack_bf16(lo_[2], lo_[3]);
            pfl[t][2] = pack_bf16(lo_[4], lo_[5]);
            pfl[t][3] = pack_bf16(lo_[6], lo_[7]);
        }

        const uint32_t vbase = stg + KARR;
        #pragma unroll
        for (int t = 0; t < 4; t++) {
            uint32_t bvh[8][2], bvl[8][2];
            #pragma unroll
            for (int j2 = 0; j2 < 4; j2++) {
                const uint32_t va = vbase + vb_off + t * (16 * VROWB) + j2 * 32;
                LDSM4T(bvh[2*j2][0], bvh[2*j2][1], bvh[2*j2+1][0], bvh[2*j2+1][1], va);
                LDSM4T(bvl[2*j2][0], bvl[2*j2][1], bvl[2*j2+1][0], bvl[2*j2+1][1], va + VARR);
            }
            #pragma unroll
            for (int nb = 0; nb < 8; nb++) {
                MMA_BF16(o[nb], pfh[t], bvh[nb]);
                MMA_BF16(o[nb], pfh[t], bvl[nb]);
                MMA_BF16(o[nb], pfl[t], bvh[nb]);
            }
        }

        __syncthreads();
        if (kt + 2 < nkt) AKV(kt + 2);
        cp_commit();
        cp_wait1();
        __syncthreads();
    }

#undef AKV
#undef ALOADV
#undef ALOADF

    const float inv0 = 1.0f / l0;
    const float inv1 = 1.0f / l1;
    const int rr0 = qt * 64 + w * 16 + (lane >> 2);
    #pragma unroll
    for (int nb = 0; nb < 8; nb++) {
        const int col = hh * HDIM + nb * 8 + (lane & 3) * 2;
        const size_t t0 = (size_t)(bb * TT + rr0) * DD + col;
        const size_t t1 = (size_t)(bb * TT + rr0 + 8) * DD + col;
        float2 y0, y1;
        y0.x = to_tf32(o[nb][0] * inv0);
        y0.y = to_tf32(o[nb][1] * inv0);
        y1.x = to_tf32(o[nb][2] * inv1);
        y1.y = to_tf32(o[nb][3] * inv1);
        *(float2*)(y + t0) = y0;
        *(float2*)(y + t1) = y1;
    }
}

// ---------------------------------------------------------------------------
extern "C" void kernel_launch(void* const* d_in, const int* in_sizes, int n_in,
                              void* d_out, int out_size) {
    const float* x      = (const float*)d_in[0];
    const float* w_attn = (const float*)d_in[1];
    const float* w_proj = (const float*)d_in[2];
    const float* w_fc   = (const float*)d_in[3];
    const float* w_out  = (const float*)d_in[4];
    const float* ln1_g  = (const float*)d_in[5];
    const float* ln1_b  = (const float*)d_in[6];
    const float* ln2_g  = (const float*)d_in[7];
    const float* ln2_b  = (const float*)d_in[8];
    float* out = (float*)d_out;

    float *p_x2, *p_y, *p_xnf, *p_fcf, *p_qk;
    float *p_waf, *p_wpf, *p_wff, *p_wof;
    __nv_bfloat16 *p_vh, *p_vl;
    cudaGetSymbolAddress((void**)&p_x2,  g_x2);
    cudaGetSymbolAddress((void**)&p_y,   g_y);
    cudaGetSymbolAddress((void**)&p_xnf, g_xnf);
    cudaGetSymbolAddress((void**)&p_fcf, g_fcf);
    cudaGetSymbolAddress((void**)&p_qk,  g_qk);
    cudaGetSymbolAddress((void**)&p_waf, g_wattnf);
    cudaGetSymbolAddress((void**)&p_wpf, g_wprojf);
    cudaGetSymbolAddress((void**)&p_wff, g_wfcf);
    cudaGetSymbolAddress((void**)&p_wof, g_woutf);
    cudaGetSymbolAddress((void**)&p_vh,  g_vh);
    cudaGetSymbolAddress((void**)&p_vl,  g_vl);

    cudaFuncSetAttribute(attn_kernel,
                         cudaFuncAttributeMaxDynamicSharedMemorySize, ATT_SMEM);
    cudaFuncSetAttribute(mm_tf32_kernel<0>,
                         cudaFuncAttributeMaxDynamicSharedMemorySize, MMT_SMEM);
    cudaFuncSetAttribute(mm_tf32_kernel<1>,
                         cudaFuncAttributeMaxDynamicSharedMemorySize, MMT_SMEM);
    cudaFuncSetAttribute(mm_tf32_kernel<2>,
                         cudaFuncAttributeMaxDynamicSharedMemorySize, MMT_SMEM);

    // weight prep (single fused launch, all tf32)
    wtrans_all_kernel<<<12288, dim3(32, 8)>>>(w_attn, w_proj, w_fc, w_out,
                                              p_waf, p_wpf, p_wff, p_wof);

    // 1) ln1 -> tf32 fp32
    lnf_kernel<<<ROWS, 256>>>(x, ln1_g, ln1_b, p_xnf);

    // 2) qkv = xn @ w_attn (tf32; q scaled fp32 / k fp32 / v bf16-split)
    mm_tf32_kernel<0><<<dim3(D3 / 128, ROWS / 128), 256, MMT_SMEM>>>(
        p_xnf, p_waf, nullptr, p_qk, p_vh, p_vl, ROWS, D3, DD);

    // 3) y = causal MHA
    attn_kernel<<<dim3(TT / 64, BB * HH), 128, ATT_SMEM>>>(p_qk, p_vh, p_vl, p_y);

    // 4) x2 = x + y @ w_proj
    mm_tf32_kernel<1><<<dim3(DD / 128, ROWS / 128), 256, MMT_SMEM>>>(
        p_y, p_wpf, x, p_x2, nullptr, nullptr, ROWS, DD, DD);

    // 5) ln2 -> tf32 fp32
    lnf_kernel<<<ROWS, 256>>>(p_x2, ln2_g, ln2_b, p_xnf);

    // 6) fc = gelu(xn @ w_fc)
    mm_tf32_kernel<2><<<dim3(D4 / 128, ROWS / 128), 256, MMT_SMEM>>>(
        p_xnf, p_wff, nullptr, p_fcf, nullptr, nullptr, ROWS, D4, DD);

    // 7) out = x2 + fc @ w_out
    mm_tf32_kernel<1><<<dim3(DD / 128, ROWS / 128), 256, MMT_SMEM>>>(
        p_fcf, p_wof, p_x2, out, nullptr, nullptr, ROWS, DD, D4);
}

// round 16
// speedup vs baseline: 1.5436x; 1.0023x over previous
#include <cuda_runtime.h>
#include <cuda_bf16.h>
#include <math.h>
#include <stdint.h>

#define BB 2
#define TT 2048
#define DD 1024
#define HH 16
#define HDIM 64
#define ROWS (BB * TT)
#define D3 (3 * DD)
#define D4 (4 * DD)

// fp32 scratch
__device__ float g_x2 [ROWS * DD];
__device__ float g_y  [ROWS * DD];       // attention out (tf32-rounded)
__device__ float g_xnf[ROWS * DD];       // ln out (tf32-rounded, reused)
__device__ float g_fcf[ROWS * D4];       // gelu out (tf32-rounded)
__device__ float g_qk [ROWS * 2 * DD];   // [q(scaled)|k] fp32 tf32-rounded
__device__ float g_wattnf[D3 * DD];      // transposed tf32 weights [N,K]
__device__ float g_wprojf[DD * DD];
__device__ float g_wfcf [D4 * DD];
__device__ float g_woutf[DD * D4];

// bf16 split V (for attention PV)
__device__ __nv_bfloat16 g_vh[ROWS * DD], g_vl[ROWS * DD];

__device__ __forceinline__ uint32_t smem_u32(const void* p) {
    uint32_t a;
    asm("{ .reg .u64 t; cvta.to.shared.u64 t, %1; cvt.u32.u64 %0, t; }"
        : "=r"(a) : "l"(p));
    return a;
}

__device__ __forceinline__ void cp16(uint32_t dst, const void* src) {
    asm volatile("cp.async.cg.shared.global [%0], [%1], 16;"
                 :: "r"(dst), "l"(src));
}
__device__ __forceinline__ void cp_commit() {
    asm volatile("cp.async.commit_group;");
}
__device__ __forceinline__ void cp_wait0() { asm volatile("cp.async.wait_group 0;"); }
__device__ __forceinline__ void cp_wait1() { asm volatile("cp.async.wait_group 1;"); }

#define LDSM4(d0, d1, d2, d3, addr)                                          \
    asm volatile("ldmatrix.sync.aligned.m8n8.x4.shared.b16 {%0,%1,%2,%3}, [%4];" \
                 : "=r"(d0), "=r"(d1), "=r"(d2), "=r"(d3) : "r"(addr))

#define LDSM4T(d0, d1, d2, d3, addr)                                         \
    asm volatile("ldmatrix.sync.aligned.m8n8.x4.trans.shared.b16 {%0,%1,%2,%3}, [%4];" \
                 : "=r"(d0), "=r"(d1), "=r"(d2), "=r"(d3) : "r"(addr))

#define MMA_BF16(c, a, b)                                                    \
    asm volatile("mma.sync.aligned.m16n8k16.row.col.f32.bf16.bf16.f32 "      \
                 "{%0,%1,%2,%3}, {%4,%5,%6,%7}, {%8,%9}, {%0,%1,%2,%3};"     \
                 : "+f"((c)[0]), "+f"((c)[1]), "+f"((c)[2]), "+f"((c)[3])    \
                 : "r"((a)[0]), "r"((a)[1]), "r"((a)[2]), "r"((a)[3]),       \
                   "r"((b)[0]), "r"((b)[1]))

#define MMA_TF32(c, a, b)                                                    \
    asm volatile("mma.sync.aligned.m16n8k8.row.col.f32.tf32.tf32.f32 "       \
                 "{%0,%1,%2,%3}, {%4,%5,%6,%7}, {%8,%9}, {%0,%1,%2,%3};"     \
                 : "+f"((c)[0]), "+f"((c)[1]), "+f"((c)[2]), "+f"((c)[3])    \
                 : "r"((a)[0]), "r"((a)[1]), "r"((a)[2]), "r"((a)[3]),       \
                   "r"((b)[0]), "r"((b)[1]))

__device__ __forceinline__ float to_tf32(float v) {
    float r;
    asm("cvt.rna.tf32.f32 %0, %1;" : "=f"(r) : "f"(v));
    return r;
}

__device__ __forceinline__ void split_bf16(float v, __nv_bfloat16& h, __nv_bfloat16& l) {
    h = __float2bfloat16(v);
    l = __float2bfloat16(v - __bfloat162float(h));
}

__device__ __forceinline__ uint32_t pack_bf16(__nv_bfloat16 a, __nv_bfloat16 b) {
    __nv_bfloat162 v; v.x = a; v.y = b;
    return *reinterpret_cast<uint32_t*>(&v);
}

__device__ __forceinline__ float gelu_exact(float x) {
    return 0.5f * x * (1.0f + erff(x * 0.70710678118654752f));
}

// ---------------------------------------------------------------------------
// Fused prep: weight transposes (tf32) + ln1.
// Grid ranges: [0,3072) w_attn | [3072,4096) w_proj | [4096,8192) w_fc |
//              [8192,12288) w_out | [12288,16384) ln1 rows
// Block (32,8) = 256 threads; one uniform __syncthreads per branch.
// ---------------------------------------------------------------------------
__global__ void prep_kernel(const float* __restrict__ Wa,
                            const float* __restrict__ Wp,
                            const float* __restrict__ Wf,
                            const float* __restrict__ Wo,
                            float* __restrict__ Ta,
                            float* __restrict__ Tp,
                            float* __restrict__ Tf,
                            float* __restrict__ To,
                            const float* __restrict__ x,
                            const float* __restrict__ g,
                            const float* __restrict__ b,
                            float* __restrict__ ln_out) {
    __shared__ float s[32][33];
    __shared__ float s_sum[8];
    __shared__ float s_sq[8];
    const int tx = threadIdx.x, ty = threadIdx.y;
    const int bid = blockIdx.x;

    if (bid < 12288) {
        const float* W;
        float* T;
        int K, N, lb;
        if (bid < 3072)      { W = Wa; T = Ta; K = DD; N = D3; lb = bid; }
        else if (bid < 4096) { W = Wp; T = Tp; K = DD; N = DD; lb = bid - 3072; }
        else if (bid < 8192) { W = Wf; T = Tf; K = DD; N = D4; lb = bid - 4096; }
        else                 { W = Wo; T = To; K = D4; N = DD; lb = bid - 8192; }
        const int nb = N / 32;
        const int n0 = (lb % nb) * 32;
        const int k0 = (lb / nb) * 32;
        #pragma unroll
        for (int i = 0; i < 4; i++)
            s[ty + 8 * i][tx] = W[(size_t)(k0 + ty + 8 * i) * N + n0 + tx];
        __syncthreads();
        #pragma unroll
        for (int i = 0; i < 4; i++)
            T[(size_t)(n0 + ty + 8 * i) * K + k0 + tx] = to_tf32(s[tx][ty + 8 * i]);
    } else {
        const int row = bid - 12288;
        const int tid = ty * 32 + tx;
        const float4* xr = (const float4*)(x + (size_t)row * DD);
        float4 v = xr[tid];
        float sm  = v.x + v.y + v.z + v.w;
        float ss = v.x * v.x + v.y * v.y + v.z * v.z + v.w * v.w;
        #pragma unroll
        for (int off = 16; off > 0; off >>= 1) {
            sm += __shfl_xor_sync(0xffffffffu, sm, off);
            ss += __shfl_xor_sync(0xffffffffu, ss, off);
        }
        if (tx == 0) { s_sum[ty] = sm; s_sq[ty] = ss; }
        __syncthreads();
        float ts = 0.f, tss = 0.f;
        #pragma unroll
        for (int i = 0; i < 8; i++) { ts += s_sum[i]; tss += s_sq[i]; }
        const float mean = ts * (1.0f / DD);
        const float var  = tss * (1.0f / DD) - mean * mean;
        const float rstd = rsqrtf(var + 1e-5f);
        float4 gv = ((const float4*)g)[tid];
        float4 bv = ((const float4*)b)[tid];
        float4 ov;
        ov.x = to_tf32((v.x - mean) * rstd * gv.x + bv.x);
        ov.y = to_tf32((v.y - mean) * rstd * gv.y + bv.y);
        ov.z = to_tf32((v.z - mean) * rstd * gv.z + bv.z);
        ov.w = to_tf32((v.w - mean) * rstd * gv.w + bv.w);
        ((float4*)(ln_out + (size_t)row * DD))[tid] = ov;
    }
}

// ---------------------------------------------------------------------------
// LayerNorm -> fp32 tf32-rounded (ln2)
// ---------------------------------------------------------------------------
__global__ void lnf_kernel(const float* __restrict__ x,
                           const float* __restrict__ g,
                           const float* __restrict__ b,
                           float* __restrict__ o) {
    __shared__ float s_sum[8];
    __shared__ float s_sq[8];
    const int row = blockIdx.x;
    const int tid = threadIdx.x;
    const float4* xr = (const float4*)(x + (size_t)row * DD);
    float4 v = xr[tid];
    float s  = v.x + v.y + v.z + v.w;
    float ss = v.x * v.x + v.y * v.y + v.z * v.z + v.w * v.w;
    #pragma unroll
    for (int off = 16; off > 0; off >>= 1) {
        s  += __shfl_xor_sync(0xffffffffu, s,  off);
        ss += __shfl_xor_sync(0xffffffffu, ss, off);
    }
    if ((tid & 31) == 0) { s_sum[tid >> 5] = s; s_sq[tid >> 5] = ss; }
    __syncthreads();
    float ts = 0.f, tss = 0.f;
    #pragma unroll
    for (int i = 0; i < 8; i++) { ts += s_sum[i]; tss += s_sq[i]; }
    const float mean = ts * (1.0f / DD);
    const float var  = tss * (1.0f / DD) - mean * mean;
    const float rstd = rsqrtf(var + 1e-5f);
    float4 gv = ((const float4*)g)[tid];
    float4 bv = ((const float4*)b)[tid];
    float4 ov;
    ov.x = to_tf32((v.x - mean) * rstd * gv.x + bv.x);
    ov.y = to_tf32((v.y - mean) * rstd * gv.y + bv.y);
    ov.z = to_tf32((v.z - mean) * rstd * gv.z + bv.z);
    ov.w = to_tf32((v.w - mean) * rstd * gv.w + bv.w);
    ((float4*)(o + (size_t)row * DD))[tid] = ov;
}

// ---------------------------------------------------------------------------
// tf32 GEMM: C = A @ B^T. 128x128 tile, K-chunk 32, 3-stage, 2 CTAs/SM.
// Single __syncthreads per chunk: [wait1, sync, issue(c+2), compute].
// EPI 0: qkv special   EPI 1: fp32 + residual   EPI 2: gelu -> tf32 fp32
// ---------------------------------------------------------------------------
#define CHUNK 32
#define TROWB 144
#define TARRB (128 * TROWB)
#define TSTAGEB (2 * TARRB)
#define TNSTAGE 3
#define MMT_SMEM (TNSTAGE * TSTAGEB)   // 110592

template<int EPI>
__global__ void __launch_bounds__(256, 2)
mm_tf32_kernel(const float* __restrict__ A, const float* __restrict__ B,
               const float* __restrict__ R, float* __restrict__ C,
               __nv_bfloat16* __restrict__ Vh, __nv_bfloat16* __restrict__ Vl,
               int M, int N, int K) {
    extern __shared__ char smem[];
    const uint32_t sbase = smem_u32(smem);

    const int tid  = threadIdx.x;
    const int lane = tid & 31;
    const int wid  = tid >> 5;
    const int wm   = wid & 3;
    const int wn   = wid >> 2;
    const int row0 = blockIdx.y * 128;
    const int col0 = blockIdx.x * 128;

    const int nch = K >> 5;

    float acc[2][8][4];
    #pragma unroll
    for (int mi = 0; mi < 2; mi++)
        #pragma unroll
        for (int ni = 0; ni < 8; ni++)
            #pragma unroll
            for (int j = 0; j < 4; j++) acc[mi][ni][j] = 0.f;

    const uint32_t a_off = (uint32_t)((wm * 32 + (lane & 15)) * TROWB + ((lane >> 4) << 4));
    const uint32_t b_off = (uint32_t)((wn * 64 + ((lane >> 4) << 3) + (lane & 7)) * TROWB
                                      + (((lane >> 3) & 1) << 4));

#define TISSUE(ch)                                                            \
    do {                                                                      \
        const int k0_ = (ch) * CHUNK;                                         \
        const uint32_t sb_ = sbase + ((ch) % TNSTAGE) * TSTAGEB;              \
        _Pragma("unroll")                                                     \
        for (int t_ = 0; t_ < 4; t_++) {                                      \
            const int idx_ = tid + t_ * 256;                                  \
            const int r_ = idx_ >> 3, c_ = idx_ & 7;                          \
            cp16(sb_ + r_ * TROWB + c_ * 16,                                  \
                 A + (size_t)(row0 + r_) * K + k0_ + c_ * 4);                 \
            cp16(sb_ + TARRB + r_ * TROWB + c_ * 16,                          \
                 B + (size_t)(col0 + r_) * K + k0_ + c_ * 4);                 \
        }                                                                     \
    } while (0)

    TISSUE(0); cp_commit();
    TISSUE(1); cp_commit();

    for (int c = 0; c < nch; c++) {
        cp_wait1();
        __syncthreads();
        if (c + 2 < nch) TISSUE(c + 2);
        cp_commit();

        const uint32_t sb = sbase + (c % TNSTAGE) * TSTAGEB;
        #pragma unroll
        for (int ks = 0; ks < 4; ks++) {
            uint32_t a[2][4];
            #pragma unroll
            for (int mi = 0; mi < 2; mi++)
                LDSM4(a[mi][0], a[mi][1], a[mi][2], a[mi][3],
                      sb + a_off + mi * (16 * TROWB) + ks * 32);
            #pragma unroll
            for (int nb = 0; nb < 4; nb++) {
                uint32_t b0, b1, b2, b3;
                LDSM4(b0, b1, b2, b3,
                      sb + TARRB + b_off + nb * (16 * TROWB) + ks * 32);
                uint32_t bq0[2] = {b0, b1};
                uint32_t bq1[2] = {b2, b3};
                #pragma unroll
                for (int mi = 0; mi < 2; mi++) {
                    MMA_TF32(acc[mi][2 * nb + 0], a[mi], bq0);
                    MMA_TF32(acc[mi][2 * nb + 1], a[mi], bq1);
                }
            }
        }
    }

#undef TISSUE

    const int r_b = row0 + wm * 32 + (lane >> 2);
    const int c_b = col0 + wn * 64 + (lane & 3) * 2;
    #pragma unroll
    for (int mi = 0; mi < 2; mi++) {
        #pragma unroll
        for (int half = 0; half < 2; half++) {
            const size_t r = (size_t)(r_b + mi * 16 + half * 8);
            #pragma unroll
            for (int ni = 0; ni < 8; ni++) {
                const int col = c_b + ni * 8;
                float v0 = acc[mi][ni][half * 2 + 0];
                float v1 = acc[mi][ni][half * 2 + 1];
                if (EPI == 0) {
                    // qkv: q (scaled) | k -> fp32 g_qk ; v -> bf16 hi/lo
                    if (col0 < 1024) {
                        float2 o;
                        o.x = to_tf32(0.125f * v0);
                        o.y = to_tf32(0.125f * v1);
                        *(float2*)(C + r * 2048 + col) = o;
                    } else if (col0 < 2048) {
                        float2 o;
                        o.x = to_tf32(v0);
                        o.y = to_tf32(v1);
                        *(float2*)(C + r * 2048 + col) = o;
                    } else {
                        const int vc = col - 2048;
                        __nv_bfloat16 h0, l0, h1, l1;
                        split_bf16(v0, h0, l0);
                        split_bf16(v1, h1, l1);
                        *(uint32_t*)(Vh + r * DD + vc) = pack_bf16(h0, h1);
                        *(uint32_t*)(Vl + r * DD + vc) = pack_bf16(l0, l1);
                    }
                } else if (EPI == 1) {
                    const float2 rv = *(const float2*)(R + r * N + col);
                    float2 o; o.x = v0 + rv.x; o.y = v1 + rv.y;
                    *(float2*)(C + r * N + col) = o;
                } else {
                    float2 o;
                    o.x = to_tf32(gelu_exact(v0));
                    o.y = to_tf32(gelu_exact(v1));
                    *(float2*)(C + r * N + col) = o;
                }
            }
        }
    }
}

// ---------------------------------------------------------------------------
// Causal flash attention: S via tf32 (fp32 Q/K), PV via bf16 3-term (V hi/lo).
// 128 threads, 3 CTAs/SM. Q pre-scaled by 0.125 in qkv epilogue.
// ---------------------------------------------------------------------------
#define KROWB 272                      // 64 fp32 + pad (16-aligned, conflict-free)
#define KARR  (64 * KROWB)             // 17408
#define VROWB 144
#define VARR  (64 * VROWB)             // 9216
#define ASTG  (KARR + 2 * VARR)        // 35840
#define ATT_SMEM (2 * ASTG)            // 71680

__global__ void __launch_bounds__(128, 3)
attn_kernel(const float* __restrict__ qk,
            const __nv_bfloat16* __restrict__ vhg,
            const __nv_bfloat16* __restrict__ vlg,
            float* __restrict__ y) {
    extern __shared__ char asmem[];
    const uint32_t sb = smem_u32(asmem);

    const int qt = (int)gridDim.x - 1 - (int)blockIdx.x;
    const int bh = blockIdx.y;
    const int bb = bh >> 4;
    const int hh = bh & 15;

    const int tid  = threadIdx.x;
    const int lane = tid & 31;
    const int w    = tid >> 5;

    const float* qptr = qk + (size_t)bb * TT * 2048 + hh * HDIM;
    const float* kptr = qk + (size_t)bb * TT * 2048 + 1024 + hh * HDIM;
    const __nv_bfloat16* vh = vhg + (size_t)bb * TT * DD + hh * HDIM;
    const __nv_bfloat16* vl = vlg + (size_t)bb * TT * DD + hh * HDIM;

    const int nkt = qt + 1;

#define ALOADF(dst, src, trow)                                                \
    do {                                                                      \
        _Pragma("unroll")                                                     \
        for (int i_ = 0; i_ < 8; i_++) {                                      \
            const int idx_ = tid + i_ * 128;                                  \
            const int r_ = idx_ >> 4, c_ = idx_ & 15;                         \
            cp16((dst) + r_ * KROWB + c_ * 16,                                \
                 (src) + (size_t)((trow) + r_) * 2048 + c_ * 4);              \
        }                                                                     \
    } while (0)

#define ALOADV(dst, src, trow)                                                \
    do {                                                                      \
        _Pragma("unroll")                                                     \
        for (int i_ = 0; i_ < 4; i_++) {                                      \
            const int idx_ = tid + i_ * 128;                                  \
            const int r_ = idx_ >> 3, c_ = idx_ & 7;                          \
            cp16((dst) + r_ * VROWB + c_ * 16,                                \
                 (src) + (size_t)((trow) + r_) * DD + c_ * 8);                \
        }                                                                     \
    } while (0)

#define AKV(kt_)                                                              \
    do {                                                                      \
        const uint32_t st_ = sb + ((kt_) & 1) * ASTG;                         \
        ALOADF(st_, kptr, (kt_) * 64);                                        \
        ALOADV(st_ + KARR, vh, (kt_) * 64);                                   \
        ALOADV(st_ + KARR + VARR, vl, (kt_) * 64);                            \
    } while (0)

    ALOADF(sb, qptr, qt * 64);
    cp_commit();
    cp_wait0();
    __syncthreads();

    uint32_t qf[8][4];
    {
        const uint32_t qa = (uint32_t)((w * 16 + (lane & 15)) * KROWB + ((lane >> 4) << 4));
        #pragma unroll
        for (int ks = 0; ks < 8; ks++)
            LDSM4(qf[ks][0], qf[ks][1], qf[ks][2], qf[ks][3], sb + qa + ks * 32);
    }
    __syncthreads();

    AKV(0);
    cp_commit();
    if (nkt > 1) AKV(1);
    cp_commit();
    cp_wait1();
    __syncthreads();

    float o[8][4];
    #pragma unroll
    for (int nb = 0; nb < 8; nb++)
        #pragma unroll
        for (int j = 0; j < 4; j++) o[nb][j] = 0.f;
    float m0 = -INFINITY, m1 = -INFINITY, l0 = 0.f, l1 = 0.f;

    const uint32_t kb_off = (uint32_t)((((lane >> 4) << 3) + (lane & 7)) * KROWB
                                       + (((lane >> 3) & 1) << 4));
    const uint32_t vb_off = (uint32_t)(((((lane >> 3) & 1) << 3) + (lane & 7)) * VROWB
                                       + ((lane >> 4) << 4));

    for (int kt = 0; kt < nkt; kt++) {
        const uint32_t stg = sb + (kt & 1) * ASTG;

        float s[8][4];
        #pragma unroll
        for (int nb = 0; nb < 8; nb++)
            #pragma unroll
            for (int j = 0; j < 4; j++) s[nb][j] = 0.f;

        #pragma unroll
        for (int ks = 0; ks < 8; ks++) {
            #pragma unroll
            for (int nb2 = 0; nb2 < 4; nb2++) {
                uint32_t b0, b1, b2, b3;
                LDSM4(b0, b1, b2, b3,
                      stg + kb_off + nb2 * (16 * KROWB) + ks * 32);
                uint32_t bq0[2] = {b0, b1};
                uint32_t bq1[2] = {b2, b3};
                MMA_TF32(s[2 * nb2 + 0], qf[ks], bq0);
                MMA_TF32(s[2 * nb2 + 1], qf[ks], bq1);
            }
        }

        if (kt == qt) {
            const int r0 = w * 16 + (lane >> 2);
            #pragma unroll
            for (int nb = 0; nb < 8; nb++) {
                const int c0 = nb * 8 + (lane & 3) * 2;
                if (c0     > r0)     s[nb][0] = -1e30f;
                if (c0 + 1 > r0)     s[nb][1] = -1e30f;
                if (c0     > r0 + 8) s[nb][2] = -1e30f;
                if (c0 + 1 > r0 + 8) s[nb][3] = -1e30f;
            }
        }

        float mx0 = -INFINITY, mx1 = -INFINITY;
        #pragma unroll
        for (int nb = 0; nb < 8; nb++) {
            mx0 = fmaxf(mx0, fmaxf(s[nb][0], s[nb][1]));
            mx1 = fmaxf(mx1, fmaxf(s[nb][2], s[nb][3]));
        }
        mx0 = fmaxf(mx0, __shfl_xor_sync(0xffffffffu, mx0, 1));
        mx0 = fmaxf(mx0, __shfl_xor_sync(0xffffffffu, mx0, 2));
        mx1 = fmaxf(mx1, __shfl_xor_sync(0xffffffffu, mx1, 1));
        mx1 = fmaxf(mx1, __shfl_xor_sync(0xffffffffu, mx1, 2));

        const float mn0 = fmaxf(m0, mx0);
        const float mn1 = fmaxf(m1, mx1);
        const float al0 = __expf(m0 - mn0);
        const float al1 = __expf(m1 - mn1);
        m0 = mn0; m1 = mn1;

        float ls0 = 0.f, ls1 = 0.f;
        #pragma unroll
        for (int nb = 0; nb < 8; nb++) {
            s[nb][0] = __expf(s[nb][0] - mn0);
            s[nb][1] = __expf(s[nb][1] - mn0);
            s[nb][2] = __expf(s[nb][2] - mn1);
            s[nb][3] = __expf(s[nb][3] - mn1);
            ls0 += s[nb][0] + s[nb][1];
            ls1 += s[nb][2] + s[nb][3];
        }
        ls0 += __shfl_xor_sync(0xffffffffu, ls0, 1);
        ls0 += __shfl_xor_sync(0xffffffffu, ls0, 2);
        ls1 += __shfl_xor_sync(0xffffffffu, ls1, 1);
        ls1 += __shfl_xor_sync(0xffffffffu, ls1, 2);
        l0 = l0 * al0 + ls0;
        l1 = l1 * al1 + ls1;

        #pragma unroll
        for (int nb = 0; nb < 8; nb++) {
            o[nb][0] *= al0; o[nb][1] *= al0;
            o[nb][2] *= al1; o[nb][3] *= al1;
        }

        uint32_t pfh[4][4], pfl[4][4];
        #pragma unroll
        for (int t = 0; t < 4; t++) {
            __nv_bfloat16 h[8], lo_[8];
            #pragma unroll
            for (int j = 0; j < 4; j++) {
                split_bf16(s[2*t][j],   h[j],     lo_[j]);
                split_bf16(s[2*t+1][j], h[4 + j], lo_[4 + j]);
            }
            pfh[t][0] = pack_bf16(h[0], h[1]);
            pfh[t][1] = pack_bf16(h[2], h[3]);
            pfh[t][2] = pack_bf16(h[4], h[5]);
            pfh[t][3] = pack_bf16(h[6], h[7]);
            pfl[t][0] = pack_bf16(lo_[0], lo_[1]);
            pfl[t][1] = pack_bf16(lo_[2], lo_[3]);
            pfl[t][2] = pack_bf16(lo_[4], lo_[5]);
            pfl[t][3] = pack_bf16(lo_[6], lo_[7]);
        }

        const uint32_t vbase = stg + KARR;
        #pragma unroll
        for (int t = 0; t < 4; t++) {
            uint32_t bvh[8][2], bvl[8][2];
            #pragma unroll
            for (int j2 = 0; j2 < 4; j2++) {
                const uint32_t va = vbase + vb_off + t * (16 * VROWB) + j2 * 32;
                LDSM4T(bvh[2*j2][0], bvh[2*j2][1], bvh[2*j2+1][0], bvh[2*j2+1][1], va);
                LDSM4T(bvl[2*j2][0], bvl[2*j2][1], bvl[2*j2+1][0], bvl[2*j2+1][1], va + VARR);
            }
            #pragma unroll
            for (int nb = 0; nb < 8; nb++) {
                MMA_BF16(o[nb], pfh[t], bvh[nb]);
                MMA_BF16(o[nb], pfh[t], bvl[nb]);
                MMA_BF16(o[nb], pfl[t], bvh[nb]);
            }
        }

        __syncthreads();
        if (kt + 2 < nkt) AKV(kt + 2);
        cp_commit();
        cp_wait1();
        __syncthreads();
    }

#undef AKV
#undef ALOADV
#undef ALOADF

    const float inv0 = 1.0f / l0;
    const float inv1 = 1.0f / l1;
    const int rr0 = qt * 64 + w * 16 + (lane >> 2);
    #pragma unroll
    for (int nb = 0; nb < 8; nb++) {
        const int col = hh * HDIM + nb * 8 + (lane & 3) * 2;
        const size_t t0 = (size_t)(bb * TT + rr0) * DD + col;
        const size_t t1 = (size_t)(bb * TT + rr0 + 8) * DD + col;
        float2 y0, y1;
        y0.x = to_tf32(o[nb][0] * inv0);
        y0.y = to_tf32(o[nb][1] * inv0);
        y1.x = to_tf32(o[nb][2] * inv1);
        y1.y = to_tf32(o[nb][3] * inv1);
        *(float2*)(y + t0) = y0;
        *(float2*)(y + t1) = y1;
    }
}

// ---------------------------------------------------------------------------
extern "C" void kernel_launch(void* const* d_in, const int* in_sizes, int n_in,
                              void* d_out, int out_size) {
    const float* x      = (const float*)d_in[0];
    const float* w_attn = (const float*)d_in[1];
    const float* w_proj = (const float*)d_in[2];
    const float* w_fc   = (const float*)d_in[3];
    const float* w_out  = (const float*)d_in[4];
    const float* ln1_g  = (const float*)d_in[5];
    const float* ln1_b  = (const float*)d_in[6];
    const float* ln2_g  = (const float*)d_in[7];
    const float* ln2_b  = (const float*)d_in[8];
    float* out = (float*)d_out;

    float *p_x2, *p_y, *p_xnf, *p_fcf, *p_qk;
    float *p_waf, *p_wpf, *p_wff, *p_wof;
    __nv_bfloat16 *p_vh, *p_vl;
    cudaGetSymbolAddress((void**)&p_x2,  g_x2);
    cudaGetSymbolAddress((void**)&p_y,   g_y);
    cudaGetSymbolAddress((void**)&p_xnf, g_xnf);
    cudaGetSymbolAddress((void**)&p_fcf, g_fcf);
    cudaGetSymbolAddress((void**)&p_qk,  g_qk);
    cudaGetSymbolAddress((void**)&p_waf, g_wattnf);
    cudaGetSymbolAddress((void**)&p_wpf, g_wprojf);
    cudaGetSymbolAddress((void**)&p_wff, g_wfcf);
    cudaGetSymbolAddress((void**)&p_wof, g_woutf);
    cudaGetSymbolAddress((void**)&p_vh,  g_vh);
    cudaGetSymbolAddress((void**)&p_vl,  g_vl);

    cudaFuncSetAttribute(attn_kernel,
                         cudaFuncAttributeMaxDynamicSharedMemorySize, ATT_SMEM);
    cudaFuncSetAttribute(mm_tf32_kernel<0>,
                         cudaFuncAttributeMaxDynamicSharedMemorySize, MMT_SMEM);
    cudaFuncSetAttribute(mm_tf32_kernel<1>,
                         cudaFuncAttributeMaxDynamicSharedMemorySize, MMT_SMEM);
    cudaFuncSetAttribute(mm_tf32_kernel<2>,
                         cudaFuncAttributeMaxDynamicSharedMemorySize, MMT_SMEM);

    // 0) fused prep: weight transposes (tf32) + ln1
    prep_kernel<<<16384, dim3(32, 8)>>>(w_attn, w_proj, w_fc, w_out,
                                        p_waf, p_wpf, p_wff, p_wof,
                                        x, ln1_g, ln1_b, p_xnf);

    // 1) qkv = xn @ w_attn (tf32; q scaled fp32 / k fp32 / v bf16-split)
    mm_tf32_kernel<0><<<dim3(D3 / 128, ROWS / 128), 256, MMT_SMEM>>>(
        p_xnf, p_waf, nullptr, p_qk, p_vh, p_vl, ROWS, D3, DD);

    // 2) y = causal MHA
    attn_kernel<<<dim3(TT / 64, BB * HH), 128, ATT_SMEM>>>(p_qk, p_vh, p_vl, p_y);

    // 3) x2 = x + y @ w_proj
    mm_tf32_kernel<1><<<dim3(DD / 128, ROWS / 128), 256, MMT_SMEM>>>(
        p_y, p_wpf, x, p_x2, nullptr, nullptr, ROWS, DD, DD);

    // 4) ln2 -> tf32 fp32
    lnf_kernel<<<ROWS, 256>>>(p_x2, ln2_g, ln2_b, p_xnf);

    // 5) fc = gelu(xn @ w_fc)
    mm_tf32_kernel<2><<<dim3(D4 / 128, ROWS / 128), 256, MMT_SMEM>>>(
        p_xnf, p_wff, nullptr, p_fcf, nullptr, nullptr, ROWS, D4, DD);

    // 6) out = x2 + fc @ w_out
    mm_tf32_kernel<1><<<dim3(DD / 128, ROWS / 128), 256, MMT_SMEM>>>(
        p_fcf, p_wof, p_x2, out, nullptr, nullptr, ROWS, DD, D4);
}

// round 17
// speedup vs baseline: 1.5449x; 1.0008x over previous
#include <cuda_runtime.h>
#include <cuda_bf16.h>
#include <math.h>
#include <stdint.h>

#define BB 2
#define TT 2048
#define DD 1024
#define HH 16
#define HDIM 64
#define ROWS (BB * TT)
#define D3 (3 * DD)
#define D4 (4 * DD)

// fp32 scratch
__device__ float g_x2 [ROWS * DD];
__device__ float g_y  [ROWS * DD];       // attention out (tf32-rounded)
__device__ float g_xnf[ROWS * DD];       // ln out (tf32-rounded, reused)
__device__ float g_fcf[ROWS * D4];       // gelu out (tf32-rounded)
__device__ float g_qk [ROWS * 2 * DD];   // [q(scaled)|k] fp32 tf32-rounded
__device__ float g_wattnf[D3 * DD];      // transposed tf32 weights [N,K]
__device__ float g_wprojf[DD * DD];
__device__ float g_wfcf [D4 * DD];
__device__ float g_woutf[DD * D4];

// bf16 split V (for attention PV)
__device__ __nv_bfloat16 g_vh[ROWS * DD], g_vl[ROWS * DD];

__device__ __forceinline__ uint32_t smem_u32(const void* p) {
    uint32_t a;
    asm("{ .reg .u64 t; cvta.to.shared.u64 t, %1; cvt.u32.u64 %0, t; }"
        : "=r"(a) : "l"(p));
    return a;
}

__device__ __forceinline__ void cp16(uint32_t dst, const void* src) {
    asm volatile("cp.async.cg.shared.global [%0], [%1], 16;"
                 :: "r"(dst), "l"(src));
}
__device__ __forceinline__ void cp_commit() {
    asm volatile("cp.async.commit_group;");
}
__device__ __forceinline__ void cp_wait0() { asm volatile("cp.async.wait_group 0;"); }
__device__ __forceinline__ void cp_wait1() { asm volatile("cp.async.wait_group 1;"); }

#define LDSM4(d0, d1, d2, d3, addr)                                          \
    asm volatile("ldmatrix.sync.aligned.m8n8.x4.shared.b16 {%0,%1,%2,%3}, [%4];" \
                 : "=r"(d0), "=r"(d1), "=r"(d2), "=r"(d3) : "r"(addr))

#define LDSM4T(d0, d1, d2, d3, addr)                                         \
    asm volatile("ldmatrix.sync.aligned.m8n8.x4.trans.shared.b16 {%0,%1,%2,%3}, [%4];" \
                 : "=r"(d0), "=r"(d1), "=r"(d2), "=r"(d3) : "r"(addr))

#define MMA_BF16(c, a, b)                                                    \
    asm volatile("mma.sync.aligned.m16n8k16.row.col.f32.bf16.bf16.f32 "      \
                 "{%0,%1,%2,%3}, {%4,%5,%6,%7}, {%8,%9}, {%0,%1,%2,%3};"     \
                 : "+f"((c)[0]), "+f"((c)[1]), "+f"((c)[2]), "+f"((c)[3])    \
                 : "r"((a)[0]), "r"((a)[1]), "r"((a)[2]), "r"((a)[3]),       \
                   "r"((b)[0]), "r"((b)[1]))

#define MMA_TF32(c, a, b)                                                    \
    asm volatile("mma.sync.aligned.m16n8k8.row.col.f32.tf32.tf32.f32 "       \
                 "{%0,%1,%2,%3}, {%4,%5,%6,%7}, {%8,%9}, {%0,%1,%2,%3};"     \
                 : "+f"((c)[0]), "+f"((c)[1]), "+f"((c)[2]), "+f"((c)[3])    \
                 : "r"((a)[0]), "r"((a)[1]), "r"((a)[2]), "r"((a)[3]),       \
                   "r"((b)[0]), "r"((b)[1]))

__device__ __forceinline__ float to_tf32(float v) {
    float r;
    asm("cvt.rna.tf32.f32 %0, %1;" : "=f"(r) : "f"(v));
    return r;
}

__device__ __forceinline__ void split_bf16(float v, __nv_bfloat16& h, __nv_bfloat16& l) {
    h = __float2bfloat16(v);
    l = __float2bfloat16(v - __bfloat162float(h));
}

__device__ __forceinline__ uint32_t pack_bf16(__nv_bfloat16 a, __nv_bfloat16 b) {
    __nv_bfloat162 v; v.x = a; v.y = b;
    return *reinterpret_cast<uint32_t*>(&v);
}

__device__ __forceinline__ float gelu_exact(float x) {
    return 0.5f * x * (1.0f + erff(x * 0.70710678118654752f));
}

// ---------------------------------------------------------------------------
// Fused prep: weight transposes (tf32) + ln1.
// Grid ranges: [0,3072) w_attn | [3072,4096) w_proj | [4096,8192) w_fc |
//              [8192,12288) w_out | [12288,16384) ln1 rows
// ---------------------------------------------------------------------------
__global__ void prep_kernel(const float* __restrict__ Wa,
                            const float* __restrict__ Wp,
                            const float* __restrict__ Wf,
                            const float* __restrict__ Wo,
                            float* __restrict__ Ta,
                            float* __restrict__ Tp,
                            float* __restrict__ Tf,
                            float* __restrict__ To,
                            const float* __restrict__ x,
                            const float* __restrict__ g,
                            const float* __restrict__ b,
                            float* __restrict__ ln_out) {
    __shared__ float s[32][33];
    __shared__ float s_sum[8];
    __shared__ float s_sq[8];
    const int tx = threadIdx.x, ty = threadIdx.y;
    const int bid = blockIdx.x;

    if (bid < 12288) {
        const float* W;
        float* T;
        int K, N, lb;
        if (bid < 3072)      { W = Wa; T = Ta; K = DD; N = D3; lb = bid; }
        else if (bid < 4096) { W = Wp; T = Tp; K = DD; N = DD; lb = bid - 3072; }
        else if (bid < 8192) { W = Wf; T = Tf; K = DD; N = D4; lb = bid - 4096; }
        else                 { W = Wo; T = To; K = D4; N = DD; lb = bid - 8192; }
        const int nb = N / 32;
        const int n0 = (lb % nb) * 32;
        const int k0 = (lb / nb) * 32;
        #pragma unroll
        for (int i = 0; i < 4; i++)
            s[ty + 8 * i][tx] = W[(size_t)(k0 + ty + 8 * i) * N + n0 + tx];
        __syncthreads();
        #pragma unroll
        for (int i = 0; i < 4; i++)
            T[(size_t)(n0 + ty + 8 * i) * K + k0 + tx] = to_tf32(s[tx][ty + 8 * i]);
    } else {
        const int row = bid - 12288;
        const int tid = ty * 32 + tx;
        const float4* xr = (const float4*)(x + (size_t)row * DD);
        float4 v = xr[tid];
        float sm  = v.x + v.y + v.z + v.w;
        float ss = v.x * v.x + v.y * v.y + v.z * v.z + v.w * v.w;
        #pragma unroll
        for (int off = 16; off > 0; off >>= 1) {
            sm += __shfl_xor_sync(0xffffffffu, sm, off);
            ss += __shfl_xor_sync(0xffffffffu, ss, off);
        }
        if (tx == 0) { s_sum[ty] = sm; s_sq[ty] = ss; }
        __syncthreads();
        float ts = 0.f, tss = 0.f;
        #pragma unroll
        for (int i = 0; i < 8; i++) { ts += s_sum[i]; tss += s_sq[i]; }
        const float mean = ts * (1.0f / DD);
        const float var  = tss * (1.0f / DD) - mean * mean;
        const float rstd = rsqrtf(var + 1e-5f);
        float4 gv = ((const float4*)g)[tid];
        float4 bv = ((const float4*)b)[tid];
        float4 ov;
        ov.x = to_tf32((v.x - mean) * rstd * gv.x + bv.x);
        ov.y = to_tf32((v.y - mean) * rstd * gv.y + bv.y);
        ov.z = to_tf32((v.z - mean) * rstd * gv.z + bv.z);
        ov.w = to_tf32((v.w - mean) * rstd * gv.w + bv.w);
        ((float4*)(ln_out + (size_t)row * DD))[tid] = ov;
    }
}

// ---------------------------------------------------------------------------
// LayerNorm -> fp32 tf32-rounded (ln2)
// ---------------------------------------------------------------------------
__global__ void lnf_kernel(const float* __restrict__ x,
                           const float* __restrict__ g,
                           const float* __restrict__ b,
                           float* __restrict__ o) {
    __shared__ float s_sum[8];
    __shared__ float s_sq[8];
    const int row = blockIdx.x;
    const int tid = threadIdx.x;
    const float4* xr = (const float4*)(x + (size_t)row * DD);
    float4 v = xr[tid];
    float s  = v.x + v.y + v.z + v.w;
    float ss = v.x * v.x + v.y * v.y + v.z * v.z + v.w * v.w;
    #pragma unroll
    for (int off = 16; off > 0; off >>= 1) {
        s  += __shfl_xor_sync(0xffffffffu, s,  off);
        ss += __shfl_xor_sync(0xffffffffu, ss, off);
    }
    if ((tid & 31) == 0) { s_sum[tid >> 5] = s; s_sq[tid >> 5] = ss; }
    __syncthreads();
    float ts = 0.f, tss = 0.f;
    #pragma unroll
    for (int i = 0; i < 8; i++) { ts += s_sum[i]; tss += s_sq[i]; }
    const float mean = ts * (1.0f / DD);
    const float var  = tss * (1.0f / DD) - mean * mean;
    const float rstd = rsqrtf(var + 1e-5f);
    float4 gv = ((const float4*)g)[tid];
    float4 bv = ((const float4*)b)[tid];
    float4 ov;
    ov.x = to_tf32((v.x - mean) * rstd * gv.x + bv.x);
    ov.y = to_tf32((v.y - mean) * rstd * gv.y + bv.y);
    ov.z = to_tf32((v.z - mean) * rstd * gv.z + bv.z);
    ov.w = to_tf32((v.w - mean) * rstd * gv.w + bv.w);
    ((float4*)(o + (size_t)row * DD))[tid] = ov;
}

// ---------------------------------------------------------------------------
// tf32 GEMM: C = A @ B^T. 128x128 tile, K-chunk 32, 3-stage, 2 CTAs/SM.
// Single __syncthreads per chunk: [wait1, sync, issue(c+2), compute].
// EPI 0: qkv special   EPI 1: fp32 + residual   EPI 2: gelu -> tf32 fp32
// ---------------------------------------------------------------------------
#define CHUNK 32
#define TROWB 144
#define TARRB (128 * TROWB)
#define TSTAGEB (2 * TARRB)
#define TNSTAGE 3
#define MMT_SMEM (TNSTAGE * TSTAGEB)   // 110592

template<int EPI>
__global__ void __launch_bounds__(256, 2)
mm_tf32_kernel(const float* __restrict__ A, const float* __restrict__ B,
               const float* __restrict__ R, float* __restrict__ C,
               __nv_bfloat16* __restrict__ Vh, __nv_bfloat16* __restrict__ Vl,
               int M, int N, int K) {
    extern __shared__ char smem[];
    const uint32_t sbase = smem_u32(smem);

    const int tid  = threadIdx.x;
    const int lane = tid & 31;
    const int wid  = tid >> 5;
    const int wm   = wid & 3;
    const int wn   = wid >> 2;
    const int row0 = blockIdx.y * 128;
    const int col0 = blockIdx.x * 128;

    const int nch = K >> 5;

    float acc[2][8][4];
    #pragma unroll
    for (int mi = 0; mi < 2; mi++)
        #pragma unroll
        for (int ni = 0; ni < 8; ni++)
            #pragma unroll
            for (int j = 0; j < 4; j++) acc[mi][ni][j] = 0.f;

    const uint32_t a_off = (uint32_t)((wm * 32 + (lane & 15)) * TROWB + ((lane >> 4) << 4));
    const uint32_t b_off = (uint32_t)((wn * 64 + ((lane >> 4) << 3) + (lane & 7)) * TROWB
                                      + (((lane >> 3) & 1) << 4));

#define TISSUE(ch)                                                            \
    do {                                                                      \
        const int k0_ = (ch) * CHUNK;                                         \
        const uint32_t sb_ = sbase + ((ch) % TNSTAGE) * TSTAGEB;              \
        _Pragma("unroll")                                                     \
        for (int t_ = 0; t_ < 4; t_++) {                                      \
            const int idx_ = tid + t_ * 256;                                  \
            const int r_ = idx_ >> 3, c_ = idx_ & 7;                          \
            cp16(sb_ + r_ * TROWB + c_ * 16,                                  \
                 A + (size_t)(row0 + r_) * K + k0_ + c_ * 4);                 \
            cp16(sb_ + TARRB + r_ * TROWB + c_ * 16,                          \
                 B + (size_t)(col0 + r_) * K + k0_ + c_ * 4);                 \
        }                                                                     \
    } while (0)

    TISSUE(0); cp_commit();
    TISSUE(1); cp_commit();

    for (int c = 0; c < nch; c++) {
        cp_wait1();
        __syncthreads();
        if (c + 2 < nch) TISSUE(c + 2);
        cp_commit();

        const uint32_t sb = sbase + (c % TNSTAGE) * TSTAGEB;
        #pragma unroll
        for (int ks = 0; ks < 4; ks++) {
            uint32_t a[2][4];
            #pragma unroll
            for (int mi = 0; mi < 2; mi++)
                LDSM4(a[mi][0], a[mi][1], a[mi][2], a[mi][3],
                      sb + a_off + mi * (16 * TROWB) + ks * 32);
            #pragma unroll
            for (int nb = 0; nb < 4; nb++) {
                uint32_t b0, b1, b2, b3;
                LDSM4(b0, b1, b2, b3,
                      sb + TARRB + b_off + nb * (16 * TROWB) + ks * 32);
                uint32_t bq0[2] = {b0, b1};
                uint32_t bq1[2] = {b2, b3};
                #pragma unroll
                for (int mi = 0; mi < 2; mi++) {
                    MMA_TF32(acc[mi][2 * nb + 0], a[mi], bq0);
                    MMA_TF32(acc[mi][2 * nb + 1], a[mi], bq1);
                }
            }
        }
    }

#undef TISSUE

    const int r_b = row0 + wm * 32 + (lane >> 2);
    const int c_b = col0 + wn * 64 + (lane & 3) * 2;
    #pragma unroll
    for (int mi = 0; mi < 2; mi++) {
        #pragma unroll
        for (int half = 0; half < 2; half++) {
            const size_t r = (size_t)(r_b + mi * 16 + half * 8);
            #pragma unroll
            for (int ni = 0; ni < 8; ni++) {
                const int col = c_b + ni * 8;
                float v0 = acc[mi][ni][half * 2 + 0];
                float v1 = acc[mi][ni][half * 2 + 1];
                if (EPI == 0) {
                    // qkv: q (scaled) | k -> fp32 g_qk ; v -> bf16 hi/lo
                    if (col0 < 1024) {
                        float2 o;
                        o.x = to_tf32(0.125f * v0);
                        o.y = to_tf32(0.125f * v1);
                        *(float2*)(C + r * 2048 + col) = o;
                    } else if (col0 < 2048) {
                        float2 o;
                        o.x = to_tf32(v0);
                        o.y = to_tf32(v1);
                        *(float2*)(C + r * 2048 + col) = o;
                    } else {
                        const int vc = col - 2048;
                        __nv_bfloat16 h0, l0, h1, l1;
                        split_bf16(v0, h0, l0);
                        split_bf16(v1, h1, l1);
                        *(uint32_t*)(Vh + r * DD + vc) = pack_bf16(h0, h1);
                        *(uint32_t*)(Vl + r * DD + vc) = pack_bf16(l0, l1);
                    }
                } else if (EPI == 1) {
                    const float2 rv = *(const float2*)(R + r * N + col);
                    float2 o; o.x = v0 + rv.x; o.y = v1 + rv.y;
                    *(float2*)(C + r * N + col) = o;
                } else {
                    float2 o;
                    o.x = to_tf32(gelu_exact(v0));
                    o.y = to_tf32(gelu_exact(v1));
                    *(float2*)(C + r * N + col) = o;
                }
            }
        }
    }
}

// ---------------------------------------------------------------------------
// Causal flash attention: S via tf32 (fp32 Q/K), PV via bf16 3-term (V hi/lo).
// 128 threads, 3 CTAs/SM. Q pre-scaled by 0.125 in qkv epilogue.
// P repack inlined per k-block (reduced register pressure vs R16).
// ---------------------------------------------------------------------------
#define KROWB 272                      // 64 fp32 + pad (16-aligned, conflict-free)
#define KARR  (64 * KROWB)             // 17408
#define VROWB 144
#define VARR  (64 * VROWB)             // 9216
#define ASTG  (KARR + 2 * VARR)        // 35840
#define ATT_SMEM (2 * ASTG)            // 71680

__global__ void __launch_bounds__(128, 3)
attn_kernel(const float* __restrict__ qk,
            const __nv_bfloat16* __restrict__ vhg,
            const __nv_bfloat16* __restrict__ vlg,
            float* __restrict__ y) {
    extern __shared__ char asmem[];
    const uint32_t sb = smem_u32(asmem);

    const int qt = (int)gridDim.x - 1 - (int)blockIdx.x;
    const int bh = blockIdx.y;
    const int bb = bh >> 4;
    const int hh = bh & 15;

    const int tid  = threadIdx.x;
    const int lane = tid & 31;
    const int w    = tid >> 5;

    const float* qptr = qk + (size_t)bb * TT * 2048 + hh * HDIM;
    const float* kptr = qk + (size_t)bb * TT * 2048 + 1024 + hh * HDIM;
    const __nv_bfloat16* vh = vhg + (size_t)bb * TT * DD + hh * HDIM;
    const __nv_bfloat16* vl = vlg + (size_t)bb * TT * DD + hh * HDIM;

    const int nkt = qt + 1;

#define ALOADF(dst, src, trow)                                                \
    do {                                                                      \
        _Pragma("unroll")                                                     \
        for (int i_ = 0; i_ < 8; i_++) {                                      \
            const int idx_ = tid + i_ * 128;                                  \
            const int r_ = idx_ >> 4, c_ = idx_ & 15;                         \
            cp16((dst) + r_ * KROWB + c_ * 16,                                \
                 (src) + (size_t)((trow) + r_) * 2048 + c_ * 4);              \
        }                                                                     \
    } while (0)

#define ALOADV(dst, src, trow)                                                \
    do {                                                                      \
        _Pragma("unroll")                                                     \
        for (int i_ = 0; i_ < 4; i_++) {                                      \
            const int idx_ = tid + i_ * 128;                                  \
            const int r_ = idx_ >> 3, c_ = idx_ & 7;                          \
            cp16((dst) + r_ * VROWB + c_ * 16,                                \
                 (src) + (size_t)((trow) + r_) * DD + c_ * 8);                \
        }                                                                     \
    } while (0)

#define AKV(kt_)                                                              \
    do {                                                                      \
        const uint32_t st_ = sb + ((kt_) & 1) * ASTG;                         \
        ALOADF(st_, kptr, (kt_) * 64);                                        \
        ALOADV(st_ + KARR, vh, (kt_) * 64);                                   \
        ALOADV(st_ + KARR + VARR, vl, (kt_) * 64);                            \
    } while (0)

    ALOADF(sb, qptr, qt * 64);
    cp_commit();
    cp_wait0();
    __syncthreads();

    uint32_t qf[8][4];
    {
        const uint32_t qa = (uint32_t)((w * 16 + (lane & 15)) * KROWB + ((lane >> 4) << 4));
        #pragma unroll
        for (int ks = 0; ks < 8; ks++)
            LDSM4(qf[ks][0], qf[ks][1], qf[ks][2], qf[ks][3], sb + qa + ks * 32);
    }
    __syncthreads();

    AKV(0);
    cp_commit();
    if (nkt > 1) AKV(1);
    cp_commit();
    cp_wait1();
    __syncthreads();

    float o[8][4];
    #pragma unroll
    for (int nb = 0; nb < 8; nb++)
        #pragma unroll
        for (int j = 0; j < 4; j++) o[nb][j] = 0.f;
    float m0 = -INFINITY, m1 = -INFINITY, l0 = 0.f, l1 = 0.f;

    const uint32_t kb_off = (uint32_t)((((lane >> 4) << 3) + (lane & 7)) * KROWB
                                       + (((lane >> 3) & 1) << 4));
    const uint32_t vb_off = (uint32_t)(((((lane >> 3) & 1) << 3) + (lane & 7)) * VROWB
                                       + ((lane >> 4) << 4));

    for (int kt = 0; kt < nkt; kt++) {
        const uint32_t stg = sb + (kt & 1) * ASTG;

        float s[8][4];
        #pragma unroll
        for (int nb = 0; nb < 8; nb++)
            #pragma unroll
            for (int j = 0; j < 4; j++) s[nb][j] = 0.f;

        #pragma unroll
        for (int ks = 0; ks < 8; ks++) {
            #pragma unroll
            for (int nb2 = 0; nb2 < 4; nb2++) {
                uint32_t b0, b1, b2, b3;
                LDSM4(b0, b1, b2, b3,
                      stg + kb_off + nb2 * (16 * KROWB) + ks * 32);
                uint32_t bq0[2] = {b0, b1};
                uint32_t bq1[2] = {b2, b3};
                MMA_TF32(s[2 * nb2 + 0], qf[ks], bq0);
                MMA_TF32(s[2 * nb2 + 1], qf[ks], bq1);
            }
        }

        if (kt == qt) {
            const int r0 = w * 16 + (lane >> 2);
            #pragma unroll
            for (int nb = 0; nb < 8; nb++) {
                const int c0 = nb * 8 + (lane & 3) * 2;
                if (c0     > r0)     s[nb][0] = -1e30f;
                if (c0 + 1 > r0)     s[nb][1] = -1e30f;
                if (c0     > r0 + 8) s[nb][2] = -1e30f;
                if (c0 + 1 > r0 + 8) s[nb][3] = -1e30f;
            }
        }

        float mx0 = -INFINITY, mx1 = -INFINITY;
        #pragma unroll
        for (int nb = 0; nb < 8; nb++) {
            mx0 = fmaxf(mx0, fmaxf(s[nb][0], s[nb][1]));
            mx1 = fmaxf(mx1, fmaxf(s[nb][2], s[nb][3]));
        }
        mx0 = fmaxf(mx0, __shfl_xor_sync(0xffffffffu, mx0, 1));
        mx0 = fmaxf(mx0, __shfl_xor_sync(0xffffffffu, mx0, 2));
        mx1 = fmaxf(mx1, __shfl_xor_sync(0xffffffffu, mx1, 1));
        mx1 = fmaxf(mx1, __shfl_xor_sync(0xffffffffu, mx1, 2));

        const float mn0 = fmaxf(m0, mx0);
        const float mn1 = fmaxf(m1, mx1);
        const float al0 = __expf(m0 - mn0);
        const float al1 = __expf(m1 - mn1);
        m0 = mn0; m1 = mn1;

        float ls0 = 0.f, ls1 = 0.f;
        #pragma unroll
        for (int nb = 0; nb < 8; nb++) {
            s[nb][0] = __expf(s[nb][0] - mn0);
            s[nb][1] = __expf(s[nb][1] - mn0);
            s[nb][2] = __expf(s[nb][2] - mn1);
            s[nb][3] = __expf(s[nb][3] - mn1);
            ls0 += s[nb][0] + s[nb][1];
            ls1 += s[nb][2] + s[nb][3];
        }
        ls0 += __shfl_xor_sync(0xffffffffu, ls0, 1);
        ls0 += __shfl_xor_sync(0xffffffffu, ls0, 2);
        ls1 += __shfl_xor_sync(0xffffffffu, ls1, 1);
        ls1 += __shfl_xor_sync(0xffffffffu, ls1, 2);
        l0 = l0 * al0 + ls0;
        l1 = l1 * al1 + ls1;

        #pragma unroll
        for (int nb = 0; nb < 8; nb++) {
            o[nb][0] *= al0; o[nb][1] *= al0;
            o[nb][2] *= al1; o[nb][3] *= al1;
        }

        // ---- O += P V (bf16 3-term), P repack inlined per k-block ----
        const uint32_t vbase = stg + KARR;
        #pragma unroll
        for (int t = 0; t < 4; t++) {
            __nv_bfloat16 h[8], lo_[8];
            #pragma unroll
            for (int j = 0; j < 4; j++) {
                split_bf16(s[2*t][j],   h[j],     lo_[j]);
                split_bf16(s[2*t+1][j], h[4 + j], lo_[4 + j]);
            }
            uint32_t pfh[4], pfl[4];
            pfh[0] = pack_bf16(h[0], h[1]);
            pfh[1] = pack_bf16(h[2], h[3]);
            pfh[2] = pack_bf16(h[4], h[5]);
            pfh[3] = pack_bf16(h[6], h[7]);
            pfl[0] = pack_bf16(lo_[0], lo_[1]);
            pfl[1] = pack_bf16(lo_[2], lo_[3]);
            pfl[2] = pack_bf16(lo_[4], lo_[5]);
            pfl[3] = pack_bf16(lo_[6], lo_[7]);

            uint32_t bvh[8][2], bvl[8][2];
            #pragma unroll
            for (int j2 = 0; j2 < 4; j2++) {
                const uint32_t va = vbase + vb_off + t * (16 * VROWB) + j2 * 32;
                LDSM4T(bvh[2*j2][0], bvh[2*j2][1], bvh[2*j2+1][0], bvh[2*j2+1][1], va);
                LDSM4T(bvl[2*j2][0], bvl[2*j2][1], bvl[2*j2+1][0], bvl[2*j2+1][1], va + VARR);
            }
            #pragma unroll
            for (int nb = 0; nb < 8; nb++) {
                MMA_BF16(o[nb], pfh, bvh[nb]);
                MMA_BF16(o[nb], pfh, bvl[nb]);
                MMA_BF16(o[nb], pfl, bvh[nb]);
            }
        }

        __syncthreads();
        if (kt + 2 < nkt) AKV(kt + 2);
        cp_commit();
        cp_wait1();
        __syncthreads();
    }

#undef AKV
#undef ALOADV
#undef ALOADF

    const float inv0 = 1.0f / l0;
    const float inv1 = 1.0f / l1;
    const int rr0 = qt * 64 + w * 16 + (lane >> 2);
    #pragma unroll
    for (int nb = 0; nb < 8; nb++) {
        const int col = hh * HDIM + nb * 8 + (lane & 3) * 2;
        const size_t t0 = (size_t)(bb * TT + rr0) * DD + col;
        const size_t t1 = (size_t)(bb * TT + rr0 + 8) * DD + col;
        float2 y0, y1;
        y0.x = to_tf32(o[nb][0] * inv0);
        y0.y = to_tf32(o[nb][1] * inv0);
        y1.x = to_tf32(o[nb][2] * inv1);
        y1.y = to_tf32(o[nb][3] * inv1);
        *(float2*)(y + t0) = y0;
        *(float2*)(y + t1) = y1;
    }
}

// ---------------------------------------------------------------------------
extern "C" void kernel_launch(void* const* d_in, const int* in_sizes, int n_in,
                              void* d_out, int out_size) {
    const float* x      = (const float*)d_in[0];
    const float* w_attn = (const float*)d_in[1];
    const float* w_proj = (const float*)d_in[2];
    const float* w_fc   = (const float*)d_in[3];
    const float* w_out  = (const float*)d_in[4];
    const float* ln1_g  = (const float*)d_in[5];
    const float* ln1_b  = (const float*)d_in[6];
    const float* ln2_g  = (const float*)d_in[7];
    const float* ln2_b  = (const float*)d_in[8];
    float* out = (float*)d_out;

    float *p_x2, *p_y, *p_xnf, *p_fcf, *p_qk;
    float *p_waf, *p_wpf, *p_wff, *p_wof;
    __nv_bfloat16 *p_vh, *p_vl;
    cudaGetSymbolAddress((void**)&p_x2,  g_x2);
    cudaGetSymbolAddress((void**)&p_y,   g_y);
    cudaGetSymbolAddress((void**)&p_xnf, g_xnf);
    cudaGetSymbolAddress((void**)&p_fcf, g_fcf);
    cudaGetSymbolAddress((void**)&p_qk,  g_qk);
    cudaGetSymbolAddress((void**)&p_waf, g_wattnf);
    cudaGetSymbolAddress((void**)&p_wpf, g_wprojf);
    cudaGetSymbolAddress((void**)&p_wff, g_wfcf);
    cudaGetSymbolAddress((void**)&p_wof, g_woutf);
    cudaGetSymbolAddress((void**)&p_vh,  g_vh);
    cudaGetSymbolAddress((void**)&p_vl,  g_vl);

    cudaFuncSetAttribute(attn_kernel,
                         cudaFuncAttributeMaxDynamicSharedMemorySize, ATT_SMEM);
    cudaFuncSetAttribute(mm_tf32_kernel<0>,
                         cudaFuncAttributeMaxDynamicSharedMemorySize, MMT_SMEM);
    cudaFuncSetAttribute(mm_tf32_kernel<1>,
                         cudaFuncAttributeMaxDynamicSharedMemorySize, MMT_SMEM);
    cudaFuncSetAttribute(mm_tf32_kernel<2>,
                         cudaFuncAttributeMaxDynamicSharedMemorySize, MMT_SMEM);

    // 0) fused prep: weight transposes (tf32) + ln1
    prep_kernel<<<16384, dim3(32, 8)>>>(w_attn, w_proj, w_fc, w_out,
                                        p_waf, p_wpf, p_wff, p_wof,
                                        x, ln1_g, ln1_b, p_xnf);

    // 1) qkv = xn @ w_attn (tf32; q scaled fp32 / k fp32 / v bf16-split)
    mm_tf32_kernel<0><<<dim3(D3 / 128, ROWS / 128), 256, MMT_SMEM>>>(
        p_xnf, p_waf, nullptr, p_qk, p_vh, p_vl, ROWS, D3, DD);

    // 2) y = causal MHA
    attn_kernel<<<dim3(TT / 64, BB * HH), 128, ATT_SMEM>>>(p_qk, p_vh, p_vl, p_y);

    // 3) x2 = x + y @ w_proj
    mm_tf32_kernel<1><<<dim3(DD / 128, ROWS / 128), 256, MMT_SMEM>>>(
        p_y, p_wpf, x, p_x2, nullptr, nullptr, ROWS, DD, DD);

    // 4) ln2 -> tf32 fp32
    lnf_kernel<<<ROWS, 256>>>(p_x2, ln2_g, ln2_b, p_xnf);

    // 5) fc = gelu(xn @ w_fc)
    mm_tf32_kernel<2><<<dim3(D4 / 128, ROWS / 128), 256, MMT_SMEM>>>(
        p_xnf, p_wff, nullptr, p_fcf, nullptr, nullptr, ROWS, D4, DD);

    // 6) out = x2 + fc @ w_out
    mm_tf32_kernel<1><<<dim3(DD / 128, ROWS / 128), 256, MMT_SMEM>>>(
        p_fcf, p_wof, p_x2, out, nullptr, nullptr, ROWS, DD, D4);
}